// round 14
// baseline (speedup 1.0000x reference)
#include <cuda_runtime.h>
#include <math.h>
#include <float.h>

typedef unsigned long long ull;

#define NPIX (32*32*1024)
#define Vv 4096

// ---- static device scratch ----
__device__ float g_frest[NPIX];
__device__ float g_r[32*32*256];      // downsampled z, layout [(b*32+c)*pnpn + p]
__device__ float g_r2[4096];          // quadrant (2x2) means of f
__device__ float g_hconst[1024];      // h0 constant per (b,c)
__device__ float g_hits[Vv];
__device__ float g_esq[Vv];
__device__ float g_Mm[5][32][16];
__device__ float g_part[512];
__device__ ull   g_bestA[32768];
__device__ ull   g_bestB[32768];

// ---- packed f32x2 helpers (FFMA2) ----
__device__ __forceinline__ ull pack2(float lo, float hi) {
    ull d;
    asm("mov.b64 %0, {%1, %2};" : "=l"(d)
        : "r"(__float_as_uint(lo)), "r"(__float_as_uint(hi)));
    return d;
}
__device__ __forceinline__ float2 unpack2(ull v) {
    unsigned int lo, hi;
    asm("mov.b64 {%0, %1}, %2;" : "=r"(lo), "=r"(hi) : "l"(v));
    return make_float2(__uint_as_float(lo), __uint_as_float(hi));
}
__device__ __forceinline__ ull fma2(ull a, ull b, ull c) {
    ull d;
    asm("fma.rn.f32x2 %0, %1, %2, %3;" : "=l"(d) : "l"(a), "l"(b), "l"(c));
    return d;
}
__device__ __forceinline__ ull add2(ull a, ull b) {
    ull d;
    asm("add.rn.f32x2 %0, %1, %2;" : "=l"(d) : "l"(a), "l"(b));
    return d;
}

__device__ __forceinline__ ull enc_key(float d, int idx) {
    unsigned u = __float_as_uint(d);
    u = (u & 0x80000000u) ? ~u : (u | 0x80000000u);
    return ((ull)u << 12) | (unsigned)idx;
}

// ================ prep ================
__global__ void __launch_bounds__(256) k_prep(const float4* __restrict__ f,
                                              float4* __restrict__ out4,
                                              const float* __restrict__ emb) {
    __shared__ float red[256];
    int t = threadIdx.x, blk = blockIdx.x;
    float s = 0.f;
    for (int i = blk*256 + t; i < NPIX/4; i += gridDim.x*256) {
        float4 v = f[i];
        ((float4*)g_frest)[i] = v;
        s = fmaf(v.x, v.x, fmaf(v.y, v.y, fmaf(v.z, v.z, fmaf(v.w, v.w, s))));
        out4[i] = make_float4(0.f, 0.f, 0.f, 0.f);
    }
    red[t] = s; __syncthreads();
    for (int o = 128; o > 0; o >>= 1) { if (t < o) red[t] += red[t+o]; __syncthreads(); }
    if (t == 0) g_part[blk] = red[0];

    {   // plane + quadrant means: one warp per (b,c) plane
        int gw = blk*8 + (t >> 5), l = t & 31;
        if (gw < 1024) {
            const float4* pf = f + gw*256;
            float s0 = 0.f, s1 = 0.f, s2 = 0.f, s3 = 0.f;
            for (int i = l; i < 256; i += 32) {
                float4 v = pf[i];
                float sv = (v.x + v.y) + (v.z + v.w);
                int q = (((i >> 3) >= 16) ? 2 : 0) + (((i & 7) >= 4) ? 1 : 0);
                if (q == 0) s0 += sv; else if (q == 1) s1 += sv;
                else if (q == 2) s2 += sv; else s3 += sv;
            }
            #pragma unroll
            for (int off = 16; off; off >>= 1) {
                s0 += __shfl_down_sync(~0u, s0, off);
                s1 += __shfl_down_sync(~0u, s1, off);
                s2 += __shfl_down_sync(~0u, s2, off);
                s3 += __shfl_down_sync(~0u, s3, off);
            }
            if (l == 0) {
                g_r[gw] = ((s0 + s1) + (s2 + s3)) * (1.f/1024.f);
                g_r2[gw*4 + 0] = s0 * (1.f/256.f);
                g_r2[gw*4 + 1] = s1 * (1.f/256.f);
                g_r2[gw*4 + 2] = s2 * (1.f/256.f);
                g_r2[gw*4 + 3] = s3 * (1.f/256.f);
            }
        }
    }
    for (int v = blk*256 + t; v < Vv; v += gridDim.x*256) {
        g_hits[v] = 0.f;
        const float* e = emb + v*32;
        float acc = 0.f;
        #pragma unroll
        for (int c = 0; c < 32; c++) acc += e[c]*e[c];
        g_esq[v] = acc;
    }
    if (blk == 0) {
        if (t < 160) {
            int si = t >> 5, r = t & 31;
            const int pns5[5] = {1,2,4,8,16};
            int pn = pns5[si];
            for (int j = 0; j < 16; j++) g_Mm[si][r][j] = 0.f;
            double scale = (double)pn / 32.0;
            double x = (r + 0.5)*scale - 0.5;
            double x0 = floor(x);
            double tt = x - x0;
            int ix0 = (int)x0;
            const double a = -0.75;
            for (int j = -1; j <= 2; j++) {
                double d = fabs(tt - (double)j);
                double w;
                if (d < 1.0)      w = (a+2.0)*d*d*d - (a+3.0)*d*d + 1.0;
                else if (d < 2.0) w = a*d*d*d - 5.0*a*d*d + 8.0*a*d - 4.0*a;
                else              w = 0.0;
                int col = ix0 + j;
                col = col < 0 ? 0 : (col > pn-1 ? pn-1 : col);
                g_Mm[si][r][col] = (float)((double)g_Mm[si][r][col] + w);
            }
        }
        if (t < 32) g_bestA[t] = ~0ull;
    }
}

// ================ k_r1: analytic r for scale 1 (merged phi0), hits0 ================
__global__ void __launch_bounds__(128) k_r1(const float* __restrict__ emb,
                                            const float* __restrict__ wgt,
                                            const float* __restrict__ bias) {
    __shared__ float ws[9216];
    __shared__ float sv[32];
    __shared__ int sidx;
    int b = blockIdx.x, t = threadIdx.x;
    for (int i = t; i < 9216; i += 128) ws[i] = wgt[i];
    if (t == 0) {
        int idx = (int)(g_bestA[b] & 0xFFFull);
        sidx = idx;
        atomicAdd(&g_hits[idx], 1.f);
    }
    __syncthreads();
    if (t < 32) sv[t] = emb[sidx*32 + t];
    __syncthreads();
    int co = t >> 2, q = t & 3;
    float acc = 0.f;
    for (int ci = 0; ci < 32; ci++) {
        const float* w = ws + co*288 + ci*9;
        float w0=w[0],w1=w[1],w2=w[2],w3=w[3],w4=w[4],w5=w[5],w6=w[6],w7=w[7],w8=w[8];
        float Sf = ((w0+w1)+(w2+w3)) + ((w4+w5)+(w6+w7)) + w8;
        float top = w0+w1+w2, bot = w6+w7+w8, lef = w0+w3+w6, rig = w2+w5+w8;
        float D;
        if (q == 0)      D = 16.f*(top+lef) - w0;
        else if (q == 1) D = 16.f*(top+rig) - w2;
        else if (q == 2) D = 16.f*(bot+lef) - w6;
        else             D = 16.f*(bot+rig) - w8;
        acc = fmaf(sv[ci], Sf - D*(1.f/256.f), acc);
    }
    float vco = sv[co];
    float r = g_r2[(b*32 + co)*4 + q] - 0.5f*vco - 0.5f*acc - 0.5f*bias[co];
    g_r[(b*32 + co)*4 + q] = r;
    if (t < 32) g_hconst[b*32 + t] = sv[t];
    if (t < 4) g_bestB[b + t*32] = ~0ull;    // reset si1 buffer (128 entries across 32 blocks)
}

// ================ argmin: par selects A(0)/B(1) output buffer ================
__global__ void __launch_bounds__(256, 2) k_argmin(const float* __restrict__ emb,
                                                   int pnpn, int G, int chunk,
                                                   int TC, int items, int mode, int par) {
    extern __shared__ float sm[];
    float4* es4   = (float4*)sm;
    float*  esq_s = sm + (size_t)TC*32;
    ull*    z2t   = (ull*)(sm + (size_t)TC*33);
    float*  sdA   = (float*)(z2t + 1024);
    float*  sdB   = sdA + 256;
    int*    svA   = (int*)(sdB + 256);
    int*    svB   = svA + 256;
    ull* bp = par ? g_bestB : g_bestA;
    int t = threadIdx.x;

    if (mode == 0) {
        for (int item = blockIdx.x; item < items; item += gridDim.x) {
            __syncthreads();
            {
                int r = t >> 3, cq = (t & 7)*4;
                float zc[4];
                #pragma unroll
                for (int q = 0; q < 4; q++) zc[q] = g_r[r*32 + cq + q];
                int i0 = cq >> 1;
                z2t[i0*32 + r]     = pack2(zc[0], zc[1]);
                z2t[(i0+1)*32 + r] = pack2(zc[2], zc[3]);
            }
            __syncthreads();
            int w = t >> 5, l = t & 31;
            ull zp[16];
            #pragma unroll
            for (int i = 0; i < 16; i++) zp[i] = z2t[i*32 + l];
            float best = FLT_MAX; int bv = 0;
            int v0 = item*chunk;
            for (int t0 = v0; t0 < v0 + chunk; t0 += TC) {
                __syncthreads();
                const float4* eg = (const float4*)(emb + (size_t)t0*32);
                for (int i = t; i < TC*8; i += 256) es4[i] = eg[i];
                for (int i = t; i < TC;   i += 256) esq_s[i] = g_esq[t0 + i];
                __syncthreads();
                for (int v = w; v < TC; v += 8) {
                    const ulonglong2* evp = (const ulonglong2*)(es4 + v*8);
                    ull a0 = 0ull, a1 = 0ull;
                    #pragma unroll
                    for (int i = 0; i < 8; i++) {
                        ulonglong2 q = evp[i];
                        a0 = fma2(zp[2*i],   q.x, a0);
                        a1 = fma2(zp[2*i+1], q.y, a1);
                    }
                    float2 pq = unpack2(add2(a0, a1));
                    float dist = fmaf(-2.f, pq.x + pq.y, esq_s[v]);
                    if (dist < best) { best = dist; bv = t0 + v; }
                }
            }
            sdA[t] = best; svA[t] = bv;
            __syncthreads();
            if (w == 0) {
                float bb = sdA[l]; int vv = svA[l];
                #pragma unroll
                for (int k = 1; k < 8; k++) {
                    float d2 = sdA[k*32 + l]; int v2 = svA[k*32 + l];
                    if (d2 < bb || (d2 == bb && v2 < vv)) { bb = d2; vv = v2; }
                }
                atomicMin(&bp[l], enc_key(bb, vv));
            }
        }
    } else {
        for (int item = blockIdx.x; item < items; item += gridDim.x) {
            __syncthreads();
            int g = item % G, vc = item / G;
            {
                int r = t >> 2, cq = (t & 3)*8;
                int n = g*64 + r;
                int b = n / pnpn, p = n - b*pnpn;
                float zc[8];
                if (mode == 2) {
                    #pragma unroll
                    for (int q = 0; q < 8; q++)
                        zc[q] = g_frest[((b*32 + cq + q) << 10) + p];
                } else {
                    #pragma unroll
                    for (int q = 0; q < 8; q++)
                        zc[q] = g_r[(b*32 + cq + q)*pnpn + p];
                }
                int i0 = cq >> 1;
                #pragma unroll
                for (int j = 0; j < 4; j++)
                    z2t[(i0+j)*64 + r] = pack2(zc[2*j], zc[2*j+1]);
            }
            __syncthreads();
            int w = t >> 5, l = t & 31;
            ull zpA[16], zpB[16];
            #pragma unroll
            for (int i = 0; i < 16; i++) {
                zpA[i] = z2t[i*64 + l];
                zpB[i] = z2t[i*64 + 32 + l];
            }
            float bestA = FLT_MAX, bestB = FLT_MAX; int bvA = 0, bvB = 0;
            int v0 = vc*chunk;
            for (int t0 = v0; t0 < v0 + chunk; t0 += TC) {
                __syncthreads();
                const float4* eg = (const float4*)(emb + (size_t)t0*32);
                for (int i = t; i < TC*8; i += 256) es4[i] = eg[i];
                for (int i = t; i < TC;   i += 256) esq_s[i] = g_esq[t0 + i];
                __syncthreads();
                for (int v = w; v < TC; v += 8) {
                    const ulonglong2* evp = (const ulonglong2*)(es4 + v*8);
                    ull a0 = 0ull, a1 = 0ull, b0 = 0ull, b1 = 0ull;
                    #pragma unroll
                    for (int i = 0; i < 8; i++) {
                        ulonglong2 q = evp[i];
                        a0 = fma2(zpA[2*i],   q.x, a0);
                        a1 = fma2(zpA[2*i+1], q.y, a1);
                        b0 = fma2(zpB[2*i],   q.x, b0);
                        b1 = fma2(zpB[2*i+1], q.y, b1);
                    }
                    float2 pa = unpack2(add2(a0, a1));
                    float dA = fmaf(-2.f, pa.x + pa.y, esq_s[v]);
                    float2 pbv = unpack2(add2(b0, b1));
                    float dB = fmaf(-2.f, pbv.x + pbv.y, esq_s[v]);
                    if (dA < bestA) { bestA = dA; bvA = t0 + v; }
                    if (dB < bestB) { bestB = dB; bvB = t0 + v; }
                }
            }
            sdA[t] = bestA; svA[t] = bvA; sdB[t] = bestB; svB[t] = bvB;
            __syncthreads();
            int w2i = t >> 5, l2 = t & 31;
            if (w2i == 0) {
                float bb = sdA[l2]; int vv = svA[l2];
                #pragma unroll
                for (int k = 1; k < 8; k++) {
                    float d2 = sdA[k*32 + l2]; int v2 = svA[k*32 + l2];
                    if (d2 < bb || (d2 == bb && v2 < vv)) { bb = d2; vv = v2; }
                }
                atomicMin(&bp[g*64 + l2], enc_key(bb, vv));
            } else if (w2i == 1) {
                float bb = sdB[l2]; int vv = svB[l2];
                #pragma unroll
                for (int k = 1; k < 8; k++) {
                    float d2 = sdB[k*32 + l2]; int v2 = svB[k*32 + l2];
                    if (d2 < bb || (d2 == bb && v2 < vv)) { bb = d2; vv = v2; }
                }
                atomicMin(&bp[g*64 + 32 + l2], enc_key(bb, vv));
            }
        }
    }
}

// ==== fused ups+phi: gather codes, bicubic in smem, conv, f_rest update, pool, reset ====
#define PHI_CI 1224   // 34*36
#define UPS_W2  9792
#define UPS_HS  12096
#define UPS_HQ  16192
#define UPS_TM  18240
#define UPS_MS  22336
#define UPS_IDX 22848
#define UPS_TOT 23104
__global__ void __launch_bounds__(256, 2) k_upsphi(const float* __restrict__ emb,
                                                   const float* __restrict__ wgt,
                                                   const float* __restrict__ bias,
                                                   int pn, int sidxM, int pn2,
                                                   float biasMul, int addc, int par) {
    extern __shared__ float sm[];
    float* in_s  = sm;                         // 8*1224
    ull*   w2    = (ull*)(sm + UPS_W2);        // 1152 ull
    float* hsave = sm + UPS_HS;                // 4*1024
    float* hq    = sm + UPS_HQ;                // 8*pnpn (<=2048)
    float* tmpu  = sm + UPS_TM;                // 8*pn*32 (<=4096)
    float* Ms    = sm + UPS_MS;                // 32*pn (<=512)
    int*   sidx  = (int*)(sm + UPS_IDX);       // pnpn (<=256)
    ull* bestR = par ? g_bestB : g_bestA;
    ull* bestW = par ? g_bestA : g_bestB;
    int blk = blockIdx.x;
    int b = blk >> 3, cg = blk & 7, t = threadIdx.x;
    int pnpn = pn*pn;
    int pn32 = pn*32;
    int pn22 = pn2*pn2;
    int s2 = 32 / pn2, s22 = s2*s2;
    float invp = 1.f / (float)s22;

    // reset NEXT scale's buffer (other ping-pong buffer — no race with reads)
    for (int i = blk*256 + t; i < 32*pn22; i += gridDim.x*256) bestW[i] = ~0ull;

    // codes for this image
    for (int j = t; j < pnpn; j += 256) sidx[j] = (int)(bestR[b*pnpn + j] & 0xFFFull);
    // bicubic matrix
    for (int i = t; i < 32*pn; i += 256) Ms[i] = g_Mm[sidxM][i/pn][i%pn];
    // weights
    for (int i = t; i < 1152; i += 256) {
        float wv = wgt[cg*1152 + i]; w2[i] = pack2(wv, wv);
    }
    // zero halo once
    for (int i = t; i < 1600; i += 256) {
        int ci = i / 200, r = i - ci*200;
        int yy, xx;
        if (r < 36)      { yy = 0;       xx = r; }
        else if (r < 72) { yy = 33;      xx = r - 36; }
        else if (r < 104){ yy = r - 71;  xx = 0; }
        else { int q = r - 104; xx = 33 + (q >> 5); yy = 1 + (q & 31); }
        in_s[ci*PHI_CI + yy*36 + xx] = 0.f;
    }
    __syncthreads();
    if (cg == 0) {
        for (int j = t; j < pnpn; j += 256) atomicAdd(&g_hits[sidx[j]], 1.f);
    }

    int y = t >> 3, x0 = (t & 7)*4;
    ull accA[4], accB[4];
    #pragma unroll
    for (int k = 0; k < 4; k++) {
        float bv = bias[cg*4 + k] * biasMul;
        ull bb = pack2(bv, bv); accA[k] = bb; accB[k] = bb;
    }
    int qo = cg >> 1, ko = (cg & 1)*4;

    for (int q4 = 0; q4 < 4; q4++) {
        // gather codes' channels for this quarter
        for (int j = t; j < 8*pnpn; j += 256) {
            int c = j / pnpn, p = j - c*pnpn;
            hq[j] = emb[(size_t)sidx[p]*32 + q4*8 + c];
        }
        __syncthreads();
        // row upsample
        for (int j = t; j < 8*pn32; j += 256) {
            int c = j / pn32; int rem = j - c*pn32;
            int h = rem >> 5; int X = rem & 31;
            float acc = 0.f;
            for (int wv = 0; wv < pn; wv++)
                acc = fmaf(Ms[X*pn + wv], hq[c*pnpn + h*pn + wv], acc);
            tmpu[j] = acc;
        }
        __syncthreads();
        // col upsample -> in_s interior (+ h0 const for merged scale)
        for (int j = t; j < 8192; j += 256) {
            int c = j >> 10, Y = (j >> 5) & 31, X = j & 31;
            float acc = 0.f;
            for (int hv = 0; hv < pn; hv++)
                acc = fmaf(Ms[Y*pn + hv], tmpu[c*pn32 + hv*32 + X], acc);
            if (addc) acc += g_hconst[b*32 + q4*8 + c];
            in_s[c*PHI_CI + (Y+1)*36 + X + 1] = acc;
        }
        __syncthreads();
        // save own-channel h planes (needed for residual writeback)
        if (q4 == qo) {
            for (int j = t; j < 4096; j += 256) {
                int k = j >> 10, p = j & 1023;
                hsave[j] = in_s[(ko + k)*PHI_CI + ((p >> 5) + 1)*36 + (p & 31) + 1];
            }
        }
        // conv accumulate over this quarter
        const ull* wbase = w2 + q4*72;
        const float* pbase = in_s + y*36 + x0;
        #pragma unroll
        for (int ci = 0; ci < 8; ci++) {
            #pragma unroll
            for (int rr = 0; rr < 3; rr++) {
                const float* row = pbase + rr*36;
                float4 u03 = *(const float4*)row;
                float2 u45 = *(const float2*)(row + 4);
                ull p0 = pack2(u03.x, u03.y);
                ull p1 = pack2(u03.y, u03.z);
                ull p2 = pack2(u03.z, u03.w);
                ull p3 = pack2(u03.w, u45.x);
                ull p4 = pack2(u45.x, u45.y);
                #pragma unroll
                for (int k = 0; k < 4; k++) {
                    ull w0 = wbase[k*288 + rr*3 + 0];
                    ull w1 = wbase[k*288 + rr*3 + 1];
                    ull wv2= wbase[k*288 + rr*3 + 2];
                    ull a = accA[k], c2 = accB[k];
                    a  = fma2(p0, w0, a);  a  = fma2(p1, w1, a);  a  = fma2(p2, wv2, a);
                    c2 = fma2(p2, w0, c2); c2 = fma2(p3, w1, c2); c2 = fma2(p4, wv2, c2);
                    accA[k] = a; accB[k] = c2;
                }
            }
            wbase += 9;
            pbase += PHI_CI;
        }
        __syncthreads();   // conv reads done before next quarter overwrites in_s
    }

    // writeback residual; reuse hsave as pooling stage
    #pragma unroll
    for (int k = 0; k < 4; k++) {
        float2 pa = unpack2(accA[k]);
        float2 pbv = unpack2(accB[k]);
        float conv[4] = {pa.x, pa.y, pbv.x, pbv.y};
        int co = cg*4 + k;
        #pragma unroll
        for (int q = 0; q < 4; q++) {
            int x = x0 + q;
            int gi = ((b*32 + co) << 10) + (y << 5) + x;
            float hval = hsave[k*1024 + (y << 5) + x];
            float newv = g_frest[gi] - (0.5f*hval + 0.5f*conv[q]);
            g_frest[gi] = newv;
            hsave[k*1024 + (y << 5) + x] = newv;   // same thread, same addr
        }
    }
    __syncthreads();
    if (pn2 < 32) {
        int w = t >> 5, l = t & 31;
        for (int o = w; o < 4*pn22; o += 8) {
            int kl = o / pn22, p = o - kl*pn22;
            int ph = p / pn2, pw2 = p - ph*pn2;
            float acc = 0.f;
            for (int e = l; e < s22; e += 32) {
                int dy = e / s2, dx = e - dy*s2;
                acc += hsave[kl*1024 + ((ph*s2 + dy) << 5) + (pw2*s2 + dx)];
            }
            #pragma unroll
            for (int off = 16; off; off >>= 1)
                acc += __shfl_down_sync(~0u, acc, off);
            if (l == 0)
                g_r[(b*32 + cg*4 + kl)*pn22 + p] = acc * invp;
        }
    }
}

// ================ final: hits5 histogram + loss + perplexity ================
__global__ void k_final(float* __restrict__ out, int osz) {
    __shared__ float red[256];
    __shared__ float hist[4096];
    int t = threadIdx.x;
    for (int v = t; v < 4096; v += 256) hist[v] = 0.f;
    __syncthreads();
    for (int n = t; n < 32768; n += 256)
        atomicAdd(&hist[(int)(g_bestB[n] & 0xFFFull)], 1.f);
    __syncthreads();

    red[t] = g_part[t] + g_part[t + 256]; __syncthreads();
    for (int o = 128; o > 0; o >>= 1) { if (t < o) red[t] += red[t+o]; __syncthreads(); }
    float S = red[0]; __syncthreads();
    float m = S / (float)NPIX;
    float h = 0.f;
    for (int k = 0; k < 16; k++) h += g_hits[t + k*256] + hist[t + k*256];
    red[t] = h; __syncthreads();
    for (int o = 128; o > 0; o >>= 1) { if (t < o) red[t] += red[t+o]; __syncthreads(); }
    float tot = red[0]; __syncthreads();
    float denom = fmaxf(tot, 1.f);
    float e = 0.f;
    for (int k = 0; k < 16; k++) {
        float p = (g_hits[t + k*256] + hist[t + k*256]) / denom;
        e += p * logf(p + 1e-10f);
    }
    red[t] = e; __syncthreads();
    for (int o = 128; o > 0; o >>= 1) { if (t < o) red[t] += red[t+o]; __syncthreads(); }
    if (t == 0) {
        float ent = red[0];
        float loss = 0.f;
        for (int si = 0; si < 6; si++) { loss = loss + 0.25f*m; loss = loss + m; }
        out[osz - 2] = loss;
        out[osz - 1] = expf(-ent);
    }
}

// ================ launcher ================
extern "C" void kernel_launch(void* const* d_in, const int* in_sizes, int n_in,
                              void* d_out, int out_size) {
    const float* f   = (const float*)d_in[0];
    const float* emb = (const float*)d_in[1];
    const float* pw  = (const float*)d_in[2];
    const float* pb  = (const float*)d_in[3];
    float* out = (float*)d_out;

    static int NBA = 0;
    if (NBA == 0) {
        int dev = 0; cudaGetDevice(&dev);
        int sms = 0;
        cudaDeviceGetAttribute(&sms, cudaDevAttrMultiProcessorCount, dev);
        if (sms <= 0) sms = 148;
        NBA = 2 * sms;
        cudaFuncSetAttribute(k_argmin, cudaFuncAttributeMaxDynamicSharedMemorySize, 82*1024);
        cudaFuncSetAttribute(k_upsphi, cudaFuncAttributeMaxDynamicSharedMemorySize, 96*1024);
    }

    const int pns[6]    = {1,2,4,8,16,32};
    const int phiSel[6] = {0,0,1,2,3,3};
    const int VSs[6]    = {128,128,32,64,16,4};

    k_prep<<<512, 256>>>((const float4*)f, (float4*)out, emb);

    for (int si = 0; si < 6; si++) {
        int pn = pns[si], pnpn = pn*pn, N = 32*pnpn;
        int VS = VSs[si], chunk = 4096 / VS;
        int TC = chunk < 512 ? chunk : 512;
        int mode, G, items;
        if (pn == 1) { mode = 0; G = 1; items = VS; }
        else {
            G = N / 64;
            items = G * VS;
            mode = (pn == 32) ? 2 : 1;
        }
        size_t smem = (size_t)TC*33*sizeof(float) + 8192 + 4096;
        int grid = items < NBA ? items : NBA;
        k_argmin<<<grid, 256, smem>>>(emb, pnpn, G, chunk, TC, items, mode, si & 1);
        if (si == 0) {
            k_r1<<<32, 128>>>(emb, pw, pb);
        } else if (si < 5) {
            size_t ps = (size_t)UPS_TOT * sizeof(float);
            k_upsphi<<<256, 256, ps>>>(emb, pw + phiSel[si]*9216, pb + phiSel[si]*32,
                                       pn, si, pns[si+1],
                                       si == 1 ? 2.f : 1.f, si == 1 ? 1 : 0, si & 1);
        }
    }
    k_final<<<1, 256>>>(out, out_size);
}

// round 15
// speedup vs baseline: 1.3143x; 1.3143x over previous
#include <cuda_runtime.h>
#include <math.h>
#include <float.h>

typedef unsigned long long ull;

#define NPIX (32*32*1024)
#define Vv 4096

// ---- static device scratch ----
__device__ float g_frest[NPIX];
__device__ float g_r[32*32*256];      // downsampled z, layout [(b*32+c)*pnpn + p]
__device__ float g_r2[4096];          // quadrant (2x2) means of f
__device__ float g_hconst[1024];      // h0 constant per (b,c)
__device__ float g_h32[NPIX];
__device__ float g_hits[Vv];
__device__ float g_esq[Vv];
__device__ float g_Mm[5][32][16];
__device__ float g_part[512];
__device__ ull   g_best[32768];

// ---- packed f32x2 helpers (FFMA2) ----
__device__ __forceinline__ ull pack2(float lo, float hi) {
    ull d;
    asm("mov.b64 %0, {%1, %2};" : "=l"(d)
        : "r"(__float_as_uint(lo)), "r"(__float_as_uint(hi)));
    return d;
}
__device__ __forceinline__ float2 unpack2(ull v) {
    unsigned int lo, hi;
    asm("mov.b64 {%0, %1}, %2;" : "=r"(lo), "=r"(hi) : "l"(v));
    return make_float2(__uint_as_float(lo), __uint_as_float(hi));
}
__device__ __forceinline__ ull fma2(ull a, ull b, ull c) {
    ull d;
    asm("fma.rn.f32x2 %0, %1, %2, %3;" : "=l"(d) : "l"(a), "l"(b), "l"(c));
    return d;
}
__device__ __forceinline__ ull add2(ull a, ull b) {
    ull d;
    asm("add.rn.f32x2 %0, %1, %2;" : "=l"(d) : "l"(a), "l"(b));
    return d;
}

__device__ __forceinline__ ull enc_key(float d, int idx) {
    unsigned u = __float_as_uint(d);
    u = (u & 0x80000000u) ? ~u : (u | 0x80000000u);
    return ((ull)u << 12) | (unsigned)idx;
}

// ================ prep ================
__global__ void __launch_bounds__(256) k_prep(const float4* __restrict__ f,
                                              float4* __restrict__ out4,
                                              const float* __restrict__ emb) {
    __shared__ float red[256];
    int t = threadIdx.x, blk = blockIdx.x;
    float s = 0.f;
    for (int i = blk*256 + t; i < NPIX/4; i += gridDim.x*256) {
        float4 v = f[i];
        ((float4*)g_frest)[i] = v;
        s = fmaf(v.x, v.x, fmaf(v.y, v.y, fmaf(v.z, v.z, fmaf(v.w, v.w, s))));
        out4[i] = make_float4(0.f, 0.f, 0.f, 0.f);
    }
    red[t] = s; __syncthreads();
    for (int o = 128; o > 0; o >>= 1) { if (t < o) red[t] += red[t+o]; __syncthreads(); }
    if (t == 0) g_part[blk] = red[0];

    {   // plane + quadrant means: one warp per (b,c) plane
        int gw = blk*8 + (t >> 5), l = t & 31;
        if (gw < 1024) {
            const float4* pf = f + gw*256;
            float s0 = 0.f, s1 = 0.f, s2 = 0.f, s3 = 0.f;
            for (int i = l; i < 256; i += 32) {
                float4 v = pf[i];
                float sv = (v.x + v.y) + (v.z + v.w);
                int q = (((i >> 3) >= 16) ? 2 : 0) + (((i & 7) >= 4) ? 1 : 0);
                if (q == 0) s0 += sv; else if (q == 1) s1 += sv;
                else if (q == 2) s2 += sv; else s3 += sv;
            }
            #pragma unroll
            for (int off = 16; off; off >>= 1) {
                s0 += __shfl_down_sync(~0u, s0, off);
                s1 += __shfl_down_sync(~0u, s1, off);
                s2 += __shfl_down_sync(~0u, s2, off);
                s3 += __shfl_down_sync(~0u, s3, off);
            }
            if (l == 0) {
                g_r[gw] = ((s0 + s1) + (s2 + s3)) * (1.f/1024.f);
                g_r2[gw*4 + 0] = s0 * (1.f/256.f);
                g_r2[gw*4 + 1] = s1 * (1.f/256.f);
                g_r2[gw*4 + 2] = s2 * (1.f/256.f);
                g_r2[gw*4 + 3] = s3 * (1.f/256.f);
            }
        }
    }
    for (int v = blk*256 + t; v < Vv; v += gridDim.x*256) {
        g_hits[v] = 0.f;
        const float* e = emb + v*32;
        float acc = 0.f;
        #pragma unroll
        for (int c = 0; c < 32; c++) acc += e[c]*e[c];
        g_esq[v] = acc;
    }
    if (blk == 0) {
        if (t < 160) {
            int si = t >> 5, r = t & 31;
            const int pns5[5] = {1,2,4,8,16};
            int pn = pns5[si];
            for (int j = 0; j < 16; j++) g_Mm[si][r][j] = 0.f;
            double scale = (double)pn / 32.0;
            double x = (r + 0.5)*scale - 0.5;
            double x0 = floor(x);
            double tt = x - x0;
            int ix0 = (int)x0;
            const double a = -0.75;
            for (int j = -1; j <= 2; j++) {
                double d = fabs(tt - (double)j);
                double w;
                if (d < 1.0)      w = (a+2.0)*d*d*d - (a+3.0)*d*d + 1.0;
                else if (d < 2.0) w = a*d*d*d - 5.0*a*d*d + 8.0*a*d - 4.0*a;
                else              w = 0.0;
                int col = ix0 + j;
                col = col < 0 ? 0 : (col > pn-1 ? pn-1 : col);
                g_Mm[si][r][col] = (float)((double)g_Mm[si][r][col] + w);
            }
        }
        if (t < 32) g_best[t] = ~0ull;
    }
}

// ================ k_r1: analytic r for scale 1 (merged phi0), hits0, g_best reset ================
// r1[b,co,q] = pool2(f) - 0.5*v_co - 0.5*sum_ci v_ci*(Wsum - D_q/256) - 0.5*b_co
__global__ void __launch_bounds__(128) k_r1(const float* __restrict__ emb,
                                            const float* __restrict__ wgt,
                                            const float* __restrict__ bias) {
    __shared__ float ws[9216];
    __shared__ float sv[32];
    __shared__ int sidx;
    int b = blockIdx.x, t = threadIdx.x;
    for (int i = t; i < 9216; i += 128) ws[i] = wgt[i];
    if (t == 0) {
        int idx = (int)(g_best[b] & 0xFFFull);
        sidx = idx;
        atomicAdd(&g_hits[idx], 1.f);
    }
    __syncthreads();
    if (t < 32) sv[t] = emb[sidx*32 + t];
    __syncthreads();
    int co = t >> 2, q = t & 3;
    float acc = 0.f;
    for (int ci = 0; ci < 32; ci++) {
        const float* w = ws + co*288 + ci*9;
        float w0=w[0],w1=w[1],w2=w[2],w3=w[3],w4=w[4],w5=w[5],w6=w[6],w7=w[7],w8=w[8];
        float Sf = ((w0+w1)+(w2+w3)) + ((w4+w5)+(w6+w7)) + w8;
        float top = w0+w1+w2, bot = w6+w7+w8, lef = w0+w3+w6, rig = w2+w5+w8;
        float D;
        if (q == 0)      D = 16.f*(top+lef) - w0;
        else if (q == 1) D = 16.f*(top+rig) - w2;
        else if (q == 2) D = 16.f*(bot+lef) - w6;
        else             D = 16.f*(bot+rig) - w8;
        acc = fmaf(sv[ci], Sf - D*(1.f/256.f), acc);
    }
    float vco = sv[co];
    float r = g_r2[(b*32 + co)*4 + q] - 0.5f*vco - 0.5f*acc - 0.5f*bias[co];
    g_r[(b*32 + co)*4 + q] = r;
    if (t < 32) g_hconst[b*32 + t] = sv[t];
    if (t < 4) g_best[b + t*32] = ~0ull;
}

// ================ argmin ================
__global__ void __launch_bounds__(256, 2) k_argmin(const float* __restrict__ emb,
                                                   int pnpn, int G, int chunk,
                                                   int TC, int items, int mode) {
    extern __shared__ float sm[];
    float4* es4   = (float4*)sm;
    float*  esq_s = sm + (size_t)TC*32;
    ull*    z2t   = (ull*)(sm + (size_t)TC*33);
    float*  sdA   = (float*)(z2t + 1024);
    float*  sdB   = sdA + 256;
    int*    svA   = (int*)(sdB + 256);
    int*    svB   = svA + 256;
    int t = threadIdx.x;

    if (mode == 0) {
        for (int item = blockIdx.x; item < items; item += gridDim.x) {
            __syncthreads();
            {
                int r = t >> 3, cq = (t & 7)*4;
                float zc[4];
                #pragma unroll
                for (int q = 0; q < 4; q++) zc[q] = g_r[r*32 + cq + q];
                int i0 = cq >> 1;
                z2t[i0*32 + r]     = pack2(zc[0], zc[1]);
                z2t[(i0+1)*32 + r] = pack2(zc[2], zc[3]);
            }
            __syncthreads();
            int w = t >> 5, l = t & 31;
            ull zp[16];
            #pragma unroll
            for (int i = 0; i < 16; i++) zp[i] = z2t[i*32 + l];
            float best = FLT_MAX; int bv = 0;
            int v0 = item*chunk;
            for (int t0 = v0; t0 < v0 + chunk; t0 += TC) {
                __syncthreads();
                const float4* eg = (const float4*)(emb + (size_t)t0*32);
                for (int i = t; i < TC*8; i += 256) es4[i] = eg[i];
                for (int i = t; i < TC;   i += 256) esq_s[i] = g_esq[t0 + i];
                __syncthreads();
                for (int v = w; v < TC; v += 8) {
                    const ulonglong2* evp = (const ulonglong2*)(es4 + v*8);
                    ull a0 = 0ull, a1 = 0ull;
                    #pragma unroll
                    for (int i = 0; i < 8; i++) {
                        ulonglong2 q = evp[i];
                        a0 = fma2(zp[2*i],   q.x, a0);
                        a1 = fma2(zp[2*i+1], q.y, a1);
                    }
                    float2 pq = unpack2(add2(a0, a1));
                    float dist = fmaf(-2.f, pq.x + pq.y, esq_s[v]);
                    if (dist < best) { best = dist; bv = t0 + v; }
                }
            }
            sdA[t] = best; svA[t] = bv;
            __syncthreads();
            if (w == 0) {
                float bb = sdA[l]; int vv = svA[l];
                #pragma unroll
                for (int k = 1; k < 8; k++) {
                    float d2 = sdA[k*32 + l]; int v2 = svA[k*32 + l];
                    if (d2 < bb || (d2 == bb && v2 < vv)) { bb = d2; vv = v2; }
                }
                atomicMin(&g_best[l], enc_key(bb, vv));
            }
        }
    } else {
        for (int item = blockIdx.x; item < items; item += gridDim.x) {
            __syncthreads();
            int g = item % G, vc = item / G;
            {
                int r = t >> 2, cq = (t & 3)*8;
                int n = g*64 + r;
                int b = n / pnpn, p = n - b*pnpn;
                float zc[8];
                if (mode == 2) {
                    #pragma unroll
                    for (int q = 0; q < 8; q++)
                        zc[q] = g_frest[((b*32 + cq + q) << 10) + p];
                } else {
                    #pragma unroll
                    for (int q = 0; q < 8; q++)
                        zc[q] = g_r[(b*32 + cq + q)*pnpn + p];
                }
                int i0 = cq >> 1;
                #pragma unroll
                for (int j = 0; j < 4; j++)
                    z2t[(i0+j)*64 + r] = pack2(zc[2*j], zc[2*j+1]);
            }
            __syncthreads();
            int w = t >> 5, l = t & 31;
            ull zpA[16], zpB[16];
            #pragma unroll
            for (int i = 0; i < 16; i++) {
                zpA[i] = z2t[i*64 + l];
                zpB[i] = z2t[i*64 + 32 + l];
            }
            float bestA = FLT_MAX, bestB = FLT_MAX; int bvA = 0, bvB = 0;
            int v0 = vc*chunk;
            for (int t0 = v0; t0 < v0 + chunk; t0 += TC) {
                __syncthreads();
                const float4* eg = (const float4*)(emb + (size_t)t0*32);
                for (int i = t; i < TC*8; i += 256) es4[i] = eg[i];
                for (int i = t; i < TC;   i += 256) esq_s[i] = g_esq[t0 + i];
                __syncthreads();
                for (int v = w; v < TC; v += 8) {
                    const ulonglong2* evp = (const ulonglong2*)(es4 + v*8);
                    ull a0 = 0ull, a1 = 0ull, b0 = 0ull, b1 = 0ull;
                    #pragma unroll
                    for (int i = 0; i < 8; i++) {
                        ulonglong2 q = evp[i];
                        a0 = fma2(zpA[2*i],   q.x, a0);
                        a1 = fma2(zpA[2*i+1], q.y, a1);
                        b0 = fma2(zpB[2*i],   q.x, b0);
                        b1 = fma2(zpB[2*i+1], q.y, b1);
                    }
                    float2 pa = unpack2(add2(a0, a1));
                    float dA = fmaf(-2.f, pa.x + pa.y, esq_s[v]);
                    float2 pbv = unpack2(add2(b0, b1));
                    float dB = fmaf(-2.f, pbv.x + pbv.y, esq_s[v]);
                    if (dA < bestA) { bestA = dA; bvA = t0 + v; }
                    if (dB < bestB) { bestB = dB; bvB = t0 + v; }
                }
            }
            sdA[t] = bestA; svA[t] = bvA; sdB[t] = bestB; svB[t] = bvB;
            __syncthreads();
            int w2i = t >> 5, l2 = t & 31;
            if (w2i == 0) {
                float bb = sdA[l2]; int vv = svA[l2];
                #pragma unroll
                for (int k = 1; k < 8; k++) {
                    float d2 = sdA[k*32 + l2]; int v2 = svA[k*32 + l2];
                    if (d2 < bb || (d2 == bb && v2 < vv)) { bb = d2; vv = v2; }
                }
                atomicMin(&g_best[g*64 + l2], enc_key(bb, vv));
            } else if (w2i == 1) {
                float bb = sdB[l2]; int vv = svB[l2];
                #pragma unroll
                for (int k = 1; k < 8; k++) {
                    float d2 = sdB[k*32 + l2]; int v2 = svB[k*32 + l2];
                    if (d2 < bb || (d2 == bb && v2 < vv)) { bb = d2; vv = v2; }
                }
                atomicMin(&g_best[g*64 + 32 + l2], enc_key(bb, vv));
            }
        }
    }
}

// ================ ups (addc: add constant h0 plane at si=1) ================
__global__ void __launch_bounds__(256) k_ups(const float* __restrict__ emb, int pn, int sidx,
                                             int addc) {
    extern __shared__ float sm[];
    int pnpn = pn * pn;
    float* hq  = sm;
    float* tmp = hq + 4*pnpn;
    float* Ms  = tmp + 4*pn*32;
    int b = blockIdx.x >> 3, cg = blockIdx.x & 7, t = threadIdx.x;
    for (int i = t; i < 32*pn; i += 256) Ms[i] = g_Mm[sidx][i/pn][i%pn];
    if (cg == 0) {
        for (int j = t; j < pnpn; j += 256) {
            int idx = (int)(g_best[b*pnpn + j] & 0xFFFull);
            atomicAdd(&g_hits[idx], 1.f);
        }
    }
    for (int j = t; j < 4*pnpn; j += 256) {
        int c = j / pnpn, p = j - c*pnpn;
        int idx = (int)(g_best[b*pnpn + p] & 0xFFFull);
        hq[j] = emb[(size_t)idx*32 + cg*4 + c];
    }
    __syncthreads();
    for (int j = t; j < 4*pn*32; j += 256) {
        int c = j / (pn*32); int rem = j - c*(pn*32);
        int h = rem >> 5; int X = rem & 31;
        float acc = 0.f;
        for (int wv = 0; wv < pn; wv++)
            acc = fmaf(Ms[X*pn + wv], hq[c*pnpn + h*pn + wv], acc);
        tmp[j] = acc;
    }
    __syncthreads();
    for (int j = t; j < 4096; j += 256) {
        int c = j >> 10, Y = (j >> 5) & 31, X = j & 31;
        float acc = 0.f;
        for (int hv = 0; hv < pn; hv++)
            acc = fmaf(Ms[Y*pn + hv], tmp[(c*pn + hv)*32 + X], acc);
        if (addc) acc += g_hconst[b*32 + cg*4 + c];
        g_h32[((b*32 + cg*4 + c) << 10) + (Y << 5) + X] = acc;
    }
}

// ==== phi: 256 blocks x 256 thr, 4 co/block, 8-plane quarters; biasMul for merged scale ====
#define PHI_CI 1224   // 34*36
__global__ void __launch_bounds__(256, 4) k_phi(const float* __restrict__ wgt,
                                                const float* __restrict__ bias,
                                                int pn2, float biasMul) {
    extern __shared__ float sm[];
    float* in_s = sm;                      // 8*1224 = 9792 floats
    ull*   w2   = (ull*)(sm + 9792);       // 1152 ull
    int blk = blockIdx.x;
    int b = blk >> 3, cg = blk & 7, t = threadIdx.x;
    int pn22 = pn2*pn2;
    int s2 = 32 / pn2, s22 = s2*s2;
    float invp = 1.f / (float)s22;

    for (int i = blk*256 + t; i < 32*pn22; i += gridDim.x*256) g_best[i] = ~0ull;

    for (int i = t; i < 1152; i += 256) {
        float wv = wgt[cg*1152 + i]; w2[i] = pack2(wv, wv);
    }

    for (int i = t; i < 1600; i += 256) {
        int ci = i / 200, r = i - ci*200;
        int yy, xx;
        if (r < 36)      { yy = 0;       xx = r; }
        else if (r < 72) { yy = 33;      xx = r - 36; }
        else if (r < 104){ yy = r - 71;  xx = 0; }
        else { int q = r - 104; xx = 33 + (q >> 5); yy = 1 + (q & 31); }
        in_s[ci*PHI_CI + yy*36 + xx] = 0.f;
    }

    int y = t >> 3, x0 = (t & 7)*4;
    ull accA[4], accB[4];
    #pragma unroll
    for (int k = 0; k < 4; k++) {
        float bv = bias[cg*4 + k] * biasMul;
        ull bb = pack2(bv, bv); accA[k] = bb; accB[k] = bb;
    }
    const float* hb = g_h32 + (size_t)b*32768;

    for (int q4 = 0; q4 < 4; q4++) {
        __syncthreads();
        for (int i = t; i < 8192; i += 256) {
            int ci = i >> 10, p = i & 1023;
            in_s[ci*PHI_CI + ((p >> 5) + 1)*36 + (p & 31) + 1]
                = hb[((q4*8 + ci) << 10) + p];
        }
        __syncthreads();
        const ull* wbase = w2 + q4*72;
        const float* pbase = in_s + y*36 + x0;
        #pragma unroll
        for (int ci = 0; ci < 8; ci++) {
            #pragma unroll
            for (int rr = 0; rr < 3; rr++) {
                const float* row = pbase + rr*36;
                float4 u03 = *(const float4*)row;
                float2 u45 = *(const float2*)(row + 4);
                ull p0 = pack2(u03.x, u03.y);
                ull p1 = pack2(u03.y, u03.z);
                ull p2 = pack2(u03.z, u03.w);
                ull p3 = pack2(u03.w, u45.x);
                ull p4 = pack2(u45.x, u45.y);
                #pragma unroll
                for (int k = 0; k < 4; k++) {
                    ull w0 = wbase[k*288 + rr*3 + 0];
                    ull w1 = wbase[k*288 + rr*3 + 1];
                    ull wv2= wbase[k*288 + rr*3 + 2];
                    ull a = accA[k], c2 = accB[k];
                    a  = fma2(p0, w0, a);  a  = fma2(p1, w1, a);  a  = fma2(p2, wv2, a);
                    c2 = fma2(p2, w0, c2); c2 = fma2(p3, w1, c2); c2 = fma2(p4, wv2, c2);
                    accA[k] = a; accB[k] = c2;
                }
            }
            wbase += 9;
            pbase += PHI_CI;
        }
    }
    __syncthreads();

    #pragma unroll
    for (int k = 0; k < 4; k++) {
        float2 pa = unpack2(accA[k]);
        float2 pbv = unpack2(accB[k]);
        float conv[4] = {pa.x, pa.y, pbv.x, pbv.y};
        int co = cg*4 + k;
        #pragma unroll
        for (int q = 0; q < 4; q++) {
            int x = x0 + q;
            int gi = ((b*32 + co) << 10) + (y << 5) + x;
            float hval = g_h32[gi];
            float newv = g_frest[gi] - (0.5f*hval + 0.5f*conv[q]);
            g_frest[gi] = newv;
            in_s[k*1024 + (y << 5) + x] = newv;
        }
    }
    __syncthreads();
    if (pn2 < 32) {
        int w = t >> 5, l = t & 31;
        for (int o = w; o < 4*pn22; o += 8) {
            int kl = o / pn22, p = o - kl*pn22;
            int ph = p / pn2, pw2 = p - ph*pn2;
            float acc = 0.f;
            for (int e = l; e < s22; e += 32) {
                int dy = e / s2, dx = e - dy*s2;
                acc += in_s[kl*1024 + ((ph*s2 + dy) << 5) + (pw2*s2 + dx)];
            }
            #pragma unroll
            for (int off = 16; off; off >>= 1)
                acc += __shfl_down_sync(~0u, acc, off);
            if (l == 0)
                g_r[(b*32 + cg*4 + kl)*pn22 + p] = acc * invp;
        }
    }
}

// ================ final: si5 hits histogram + loss + perplexity ================
__global__ void k_final(float* __restrict__ out, int osz) {
    __shared__ float red[256];
    __shared__ float hist[4096];
    int t = threadIdx.x;
    for (int v = t; v < 4096; v += 256) hist[v] = 0.f;
    __syncthreads();
    for (int n = t; n < 32768; n += 256)
        atomicAdd(&hist[(int)(g_best[n] & 0xFFFull)], 1.f);
    __syncthreads();

    red[t] = g_part[t] + g_part[t + 256]; __syncthreads();
    for (int o = 128; o > 0; o >>= 1) { if (t < o) red[t] += red[t+o]; __syncthreads(); }
    float S = red[0]; __syncthreads();
    float m = S / (float)NPIX;
    float h = 0.f;
    for (int k = 0; k < 16; k++) h += g_hits[t + k*256] + hist[t + k*256];
    red[t] = h; __syncthreads();
    for (int o = 128; o > 0; o >>= 1) { if (t < o) red[t] += red[t+o]; __syncthreads(); }
    float tot = red[0]; __syncthreads();
    float denom = fmaxf(tot, 1.f);
    float e = 0.f;
    for (int k = 0; k < 16; k++) {
        float p = (g_hits[t + k*256] + hist[t + k*256]) / denom;
        e += p * logf(p + 1e-10f);
    }
    red[t] = e; __syncthreads();
    for (int o = 128; o > 0; o >>= 1) { if (t < o) red[t] += red[t+o]; __syncthreads(); }
    if (t == 0) {
        float ent = red[0];
        float loss = 0.f;
        for (int si = 0; si < 6; si++) { loss = loss + 0.25f*m; loss = loss + m; }
        out[osz - 2] = loss;
        out[osz - 1] = expf(-ent);
    }
}

// ================ launcher ================
extern "C" void kernel_launch(void* const* d_in, const int* in_sizes, int n_in,
                              void* d_out, int out_size) {
    const float* f   = (const float*)d_in[0];
    const float* emb = (const float*)d_in[1];
    const float* pw  = (const float*)d_in[2];
    const float* pb  = (const float*)d_in[3];
    float* out = (float*)d_out;

    static int NBA = 0;
    if (NBA == 0) {
        int dev = 0; cudaGetDevice(&dev);
        int sms = 0;
        cudaDeviceGetAttribute(&sms, cudaDevAttrMultiProcessorCount, dev);
        if (sms <= 0) sms = 148;
        NBA = 2 * sms;
        cudaFuncSetAttribute(k_argmin, cudaFuncAttributeMaxDynamicSharedMemorySize, 82*1024);
        cudaFuncSetAttribute(k_phi,    cudaFuncAttributeMaxDynamicSharedMemorySize, 52*1024);
        cudaFuncSetAttribute(k_ups,    cudaFuncAttributeMaxDynamicSharedMemorySize, 16*1024);
    }

    const int pns[6]    = {1,2,4,8,16,32};
    const int phiSel[6] = {0,0,1,2,3,3};
    const int VSs[6]    = {128,128,32,64,16,4};

    k_prep<<<512, 256>>>((const float4*)f, (float4*)out, emb);

    for (int si = 0; si < 6; si++) {
        int pn = pns[si], pnpn = pn*pn, N = 32*pnpn;
        int VS = VSs[si], chunk = 4096 / VS;
        int TC = chunk < 512 ? chunk : 512;
        int mode, G, items;
        if (pn == 1) { mode = 0; G = 1; items = VS; }
        else {
            G = N / 64;
            items = G * VS;
            mode = (pn == 32) ? 2 : 1;
        }
        size_t smem = (size_t)TC*33*sizeof(float) + 8192 + 4096;
        int grid = items < NBA ? items : NBA;
        k_argmin<<<grid, 256, smem>>>(emb, pnpn, G, chunk, TC, items, mode);
        if (si == 0) {
            k_r1<<<32, 128>>>(emb, pw, pb);
        } else if (si < 5) {
            size_t us = (size_t)(4*pnpn + 4*pn*32 + 32*pn) * sizeof(float);
            k_ups<<<256, 256, us>>>(emb, pn, si, si == 1 ? 1 : 0);
            size_t ps = (size_t)(9792 + 2304) * sizeof(float);
            k_phi<<<256, 256, ps>>>(pw + phiSel[si]*9216, pb + phiSel[si]*32,
                                    pns[si+1], si == 1 ? 2.f : 1.f);
        }
    }
    k_final<<<1, 256>>>(out, out_size);
}

// round 16
// speedup vs baseline: 1.4065x; 1.0702x over previous
#include <cuda_runtime.h>
#include <math.h>
#include <float.h>

typedef unsigned long long ull;

#define NPIX (32*32*1024)
#define Vv 4096

// ---- static device scratch ----
__device__ float g_frest[NPIX];
__device__ float g_r[32*32*256];      // downsampled z, layout [(b*32+c)*pnpn + p]
__device__ float g_r2[4096];          // quadrant (2x2) means of f
__device__ float g_hconst[1024];      // h0 constant per (b,c)
__device__ float g_h32[NPIX];
__device__ float g_hits[Vv];
__device__ float g_esq[Vv];
__device__ float g_Mm[5][32][16];
__device__ float g_part[512];
__device__ ull   g_best[32768];

// ---- packed f32x2 helpers (FFMA2) ----
__device__ __forceinline__ ull pack2(float lo, float hi) {
    ull d;
    asm("mov.b64 %0, {%1, %2};" : "=l"(d)
        : "r"(__float_as_uint(lo)), "r"(__float_as_uint(hi)));
    return d;
}
__device__ __forceinline__ float2 unpack2(ull v) {
    unsigned int lo, hi;
    asm("mov.b64 {%0, %1}, %2;" : "=r"(lo), "=r"(hi) : "l"(v));
    return make_float2(__uint_as_float(lo), __uint_as_float(hi));
}
__device__ __forceinline__ ull fma2(ull a, ull b, ull c) {
    ull d;
    asm("fma.rn.f32x2 %0, %1, %2, %3;" : "=l"(d) : "l"(a), "l"(b), "l"(c));
    return d;
}
__device__ __forceinline__ ull add2(ull a, ull b) {
    ull d;
    asm("add.rn.f32x2 %0, %1, %2;" : "=l"(d) : "l"(a), "l"(b));
    return d;
}

__device__ __forceinline__ ull enc_key(float d, int idx) {
    unsigned u = __float_as_uint(d);
    u = (u & 0x80000000u) ? ~u : (u | 0x80000000u);
    return ((ull)u << 12) | (unsigned)idx;
}

// ================ prep ================
__global__ void __launch_bounds__(256) k_prep(const float4* __restrict__ f,
                                              float4* __restrict__ out4,
                                              const float* __restrict__ emb) {
    __shared__ float red[256];
    int t = threadIdx.x, blk = blockIdx.x;
    float s = 0.f;
    for (int i = blk*256 + t; i < NPIX/4; i += gridDim.x*256) {
        float4 v = f[i];
        ((float4*)g_frest)[i] = v;
        s = fmaf(v.x, v.x, fmaf(v.y, v.y, fmaf(v.z, v.z, fmaf(v.w, v.w, s))));
        out4[i] = make_float4(0.f, 0.f, 0.f, 0.f);
    }
    red[t] = s; __syncthreads();
    for (int o = 128; o > 0; o >>= 1) { if (t < o) red[t] += red[t+o]; __syncthreads(); }
    if (t == 0) g_part[blk] = red[0];

    {   // plane + quadrant means: one warp per (b,c) plane
        int gw = blk*8 + (t >> 5), l = t & 31;
        if (gw < 1024) {
            const float4* pf = f + gw*256;
            float s0 = 0.f, s1 = 0.f, s2 = 0.f, s3 = 0.f;
            for (int i = l; i < 256; i += 32) {
                float4 v = pf[i];
                float sv = (v.x + v.y) + (v.z + v.w);
                int q = (((i >> 3) >= 16) ? 2 : 0) + (((i & 7) >= 4) ? 1 : 0);
                if (q == 0) s0 += sv; else if (q == 1) s1 += sv;
                else if (q == 2) s2 += sv; else s3 += sv;
            }
            #pragma unroll
            for (int off = 16; off; off >>= 1) {
                s0 += __shfl_down_sync(~0u, s0, off);
                s1 += __shfl_down_sync(~0u, s1, off);
                s2 += __shfl_down_sync(~0u, s2, off);
                s3 += __shfl_down_sync(~0u, s3, off);
            }
            if (l == 0) {
                g_r[gw] = ((s0 + s1) + (s2 + s3)) * (1.f/1024.f);
                g_r2[gw*4 + 0] = s0 * (1.f/256.f);
                g_r2[gw*4 + 1] = s1 * (1.f/256.f);
                g_r2[gw*4 + 2] = s2 * (1.f/256.f);
                g_r2[gw*4 + 3] = s3 * (1.f/256.f);
            }
        }
    }
    for (int v = blk*256 + t; v < Vv; v += gridDim.x*256) {
        g_hits[v] = 0.f;
        const float* e = emb + v*32;
        float acc = 0.f;
        #pragma unroll
        for (int c = 0; c < 32; c++) acc += e[c]*e[c];
        g_esq[v] = acc;
    }
    if (blk == 0) {
        if (t < 160) {
            int si = t >> 5, r = t & 31;
            const int pns5[5] = {1,2,4,8,16};
            int pn = pns5[si];
            for (int j = 0; j < 16; j++) g_Mm[si][r][j] = 0.f;
            double scale = (double)pn / 32.0;
            double x = (r + 0.5)*scale - 0.5;
            double x0 = floor(x);
            double tt = x - x0;
            int ix0 = (int)x0;
            const double a = -0.75;
            for (int j = -1; j <= 2; j++) {
                double d = fabs(tt - (double)j);
                double w;
                if (d < 1.0)      w = (a+2.0)*d*d*d - (a+3.0)*d*d + 1.0;
                else if (d < 2.0) w = a*d*d*d - 5.0*a*d*d + 8.0*a*d - 4.0*a;
                else              w = 0.0;
                int col = ix0 + j;
                col = col < 0 ? 0 : (col > pn-1 ? pn-1 : col);
                g_Mm[si][r][col] = (float)((double)g_Mm[si][r][col] + w);
            }
        }
        if (t < 32) g_best[t] = ~0ull;
    }
}

// ================ k_r1: analytic r for scale 1 (merged phi0), hits0, g_best reset ================
// r1[b,co,q] = pool2(f) - 0.5*v_co - 0.5*sum_ci v_ci*(Wsum - D_q/256) - 0.5*b_co
__global__ void __launch_bounds__(128) k_r1(const float* __restrict__ emb,
                                            const float* __restrict__ wgt,
                                            const float* __restrict__ bias) {
    __shared__ float ws[9216];
    __shared__ float sv[32];
    __shared__ int sidx;
    int b = blockIdx.x, t = threadIdx.x;
    for (int i = t; i < 9216; i += 128) ws[i] = wgt[i];
    if (t == 0) {
        int idx = (int)(g_best[b] & 0xFFFull);
        sidx = idx;
        atomicAdd(&g_hits[idx], 1.f);
    }
    __syncthreads();
    if (t < 32) sv[t] = emb[sidx*32 + t];
    __syncthreads();
    int co = t >> 2, q = t & 3;
    float acc = 0.f;
    for (int ci = 0; ci < 32; ci++) {
        const float* w = ws + co*288 + ci*9;
        float w0=w[0],w1=w[1],w2=w[2],w3=w[3],w4=w[4],w5=w[5],w6=w[6],w7=w[7],w8=w[8];
        float Sf = ((w0+w1)+(w2+w3)) + ((w4+w5)+(w6+w7)) + w8;
        float top = w0+w1+w2, bot = w6+w7+w8, lef = w0+w3+w6, rig = w2+w5+w8;
        float D;
        if (q == 0)      D = 16.f*(top+lef) - w0;
        else if (q == 1) D = 16.f*(top+rig) - w2;
        else if (q == 2) D = 16.f*(bot+lef) - w6;
        else             D = 16.f*(bot+rig) - w8;
        acc = fmaf(sv[ci], Sf - D*(1.f/256.f), acc);
    }
    float vco = sv[co];
    float r = g_r2[(b*32 + co)*4 + q] - 0.5f*vco - 0.5f*acc - 0.5f*bias[co];
    g_r[(b*32 + co)*4 + q] = r;
    if (t < 32) g_hconst[b*32 + t] = sv[t];
    if (t < 4) g_best[b + t*32] = ~0ull;
}

// ================ argmin ================
__global__ void __launch_bounds__(256, 2) k_argmin(const float* __restrict__ emb,
                                                   int pnpn, int G, int chunk,
                                                   int TC, int items, int mode) {
    extern __shared__ float sm[];
    float4* es4   = (float4*)sm;
    float*  esq_s = sm + (size_t)TC*32;
    ull*    z2t   = (ull*)(sm + (size_t)TC*33);
    float*  sdA   = (float*)(z2t + 1024);
    float*  sdB   = sdA + 256;
    int*    svA   = (int*)(sdB + 256);
    int*    svB   = svA + 256;
    int t = threadIdx.x;

    if (mode == 0) {
        for (int item = blockIdx.x; item < items; item += gridDim.x) {
            __syncthreads();
            {
                int r = t >> 3, cq = (t & 7)*4;
                float zc[4];
                #pragma unroll
                for (int q = 0; q < 4; q++) zc[q] = g_r[r*32 + cq + q];
                int i0 = cq >> 1;
                z2t[i0*32 + r]     = pack2(zc[0], zc[1]);
                z2t[(i0+1)*32 + r] = pack2(zc[2], zc[3]);
            }
            __syncthreads();
            int w = t >> 5, l = t & 31;
            ull zp[16];
            #pragma unroll
            for (int i = 0; i < 16; i++) zp[i] = z2t[i*32 + l];
            float best = FLT_MAX; int bv = 0;
            int v0 = item*chunk;
            for (int t0 = v0; t0 < v0 + chunk; t0 += TC) {
                __syncthreads();
                const float4* eg = (const float4*)(emb + (size_t)t0*32);
                for (int i = t; i < TC*8; i += 256) es4[i] = eg[i];
                for (int i = t; i < TC;   i += 256) esq_s[i] = g_esq[t0 + i];
                __syncthreads();
                for (int v = w; v < TC; v += 8) {
                    const ulonglong2* evp = (const ulonglong2*)(es4 + v*8);
                    ull a0 = 0ull, a1 = 0ull;
                    #pragma unroll
                    for (int i = 0; i < 8; i++) {
                        ulonglong2 q = evp[i];
                        a0 = fma2(zp[2*i],   q.x, a0);
                        a1 = fma2(zp[2*i+1], q.y, a1);
                    }
                    float2 pq = unpack2(add2(a0, a1));
                    float dist = fmaf(-2.f, pq.x + pq.y, esq_s[v]);
                    if (dist < best) { best = dist; bv = t0 + v; }
                }
            }
            sdA[t] = best; svA[t] = bv;
            __syncthreads();
            if (w == 0) {
                float bb = sdA[l]; int vv = svA[l];
                #pragma unroll
                for (int k = 1; k < 8; k++) {
                    float d2 = sdA[k*32 + l]; int v2 = svA[k*32 + l];
                    if (d2 < bb || (d2 == bb && v2 < vv)) { bb = d2; vv = v2; }
                }
                atomicMin(&g_best[l], enc_key(bb, vv));
            }
        }
    } else {
        for (int item = blockIdx.x; item < items; item += gridDim.x) {
            __syncthreads();
            int g = item % G, vc = item / G;
            {
                int r = t >> 2, cq = (t & 3)*8;
                int n = g*64 + r;
                int b = n / pnpn, p = n - b*pnpn;
                float zc[8];
                if (mode == 2) {
                    #pragma unroll
                    for (int q = 0; q < 8; q++)
                        zc[q] = g_frest[((b*32 + cq + q) << 10) + p];
                } else {
                    #pragma unroll
                    for (int q = 0; q < 8; q++)
                        zc[q] = g_r[(b*32 + cq + q)*pnpn + p];
                }
                int i0 = cq >> 1;
                #pragma unroll
                for (int j = 0; j < 4; j++)
                    z2t[(i0+j)*64 + r] = pack2(zc[2*j], zc[2*j+1]);
            }
            __syncthreads();
            int w = t >> 5, l = t & 31;
            ull zpA[16], zpB[16];
            #pragma unroll
            for (int i = 0; i < 16; i++) {
                zpA[i] = z2t[i*64 + l];
                zpB[i] = z2t[i*64 + 32 + l];
            }
            float bestA = FLT_MAX, bestB = FLT_MAX; int bvA = 0, bvB = 0;
            int v0 = vc*chunk;
            for (int t0 = v0; t0 < v0 + chunk; t0 += TC) {
                __syncthreads();
                const float4* eg = (const float4*)(emb + (size_t)t0*32);
                for (int i = t; i < TC*8; i += 256) es4[i] = eg[i];
                for (int i = t; i < TC;   i += 256) esq_s[i] = g_esq[t0 + i];
                __syncthreads();
                for (int v = w; v < TC; v += 8) {
                    const ulonglong2* evp = (const ulonglong2*)(es4 + v*8);
                    ull a0 = 0ull, a1 = 0ull, b0 = 0ull, b1 = 0ull;
                    #pragma unroll
                    for (int i = 0; i < 8; i++) {
                        ulonglong2 q = evp[i];
                        a0 = fma2(zpA[2*i],   q.x, a0);
                        a1 = fma2(zpA[2*i+1], q.y, a1);
                        b0 = fma2(zpB[2*i],   q.x, b0);
                        b1 = fma2(zpB[2*i+1], q.y, b1);
                    }
                    float2 pa = unpack2(add2(a0, a1));
                    float dA = fmaf(-2.f, pa.x + pa.y, esq_s[v]);
                    float2 pbv = unpack2(add2(b0, b1));
                    float dB = fmaf(-2.f, pbv.x + pbv.y, esq_s[v]);
                    if (dA < bestA) { bestA = dA; bvA = t0 + v; }
                    if (dB < bestB) { bestB = dB; bvB = t0 + v; }
                }
            }
            sdA[t] = bestA; svA[t] = bvA; sdB[t] = bestB; svB[t] = bvB;
            __syncthreads();
            int w2i = t >> 5, l2 = t & 31;
            if (w2i == 0) {
                float bb = sdA[l2]; int vv = svA[l2];
                #pragma unroll
                for (int k = 1; k < 8; k++) {
                    float d2 = sdA[k*32 + l2]; int v2 = svA[k*32 + l2];
                    if (d2 < bb || (d2 == bb && v2 < vv)) { bb = d2; vv = v2; }
                }
                atomicMin(&g_best[g*64 + l2], enc_key(bb, vv));
            } else if (w2i == 1) {
                float bb = sdB[l2]; int vv = svB[l2];
                #pragma unroll
                for (int k = 1; k < 8; k++) {
                    float d2 = sdB[k*32 + l2]; int v2 = svB[k*32 + l2];
                    if (d2 < bb || (d2 == bb && v2 < vv)) { bb = d2; vv = v2; }
                }
                atomicMin(&g_best[g*64 + 32 + l2], enc_key(bb, vv));
            }
        }
    }
}

// ================ ups (addc: add constant h0 plane at si=1) ================
__global__ void __launch_bounds__(256) k_ups(const float* __restrict__ emb, int pn, int sidx,
                                             int addc) {
    extern __shared__ float sm[];
    int pnpn = pn * pn;
    float* hq  = sm;
    float* tmp = hq + 4*pnpn;
    float* Ms  = tmp + 4*pn*32;
    int b = blockIdx.x >> 3, cg = blockIdx.x & 7, t = threadIdx.x;
    for (int i = t; i < 32*pn; i += 256) Ms[i] = g_Mm[sidx][i/pn][i%pn];
    if (cg == 0) {
        for (int j = t; j < pnpn; j += 256) {
            int idx = (int)(g_best[b*pnpn + j] & 0xFFFull);
            atomicAdd(&g_hits[idx], 1.f);
        }
    }
    for (int j = t; j < 4*pnpn; j += 256) {
        int c = j / pnpn, p = j - c*pnpn;
        int idx = (int)(g_best[b*pnpn + p] & 0xFFFull);
        hq[j] = emb[(size_t)idx*32 + cg*4 + c];
    }
    __syncthreads();
    for (int j = t; j < 4*pn*32; j += 256) {
        int c = j / (pn*32); int rem = j - c*(pn*32);
        int h = rem >> 5; int X = rem & 31;
        float acc = 0.f;
        for (int wv = 0; wv < pn; wv++)
            acc = fmaf(Ms[X*pn + wv], hq[c*pnpn + h*pn + wv], acc);
        tmp[j] = acc;
    }
    __syncthreads();
    for (int j = t; j < 4096; j += 256) {
        int c = j >> 10, Y = (j >> 5) & 31, X = j & 31;
        float acc = 0.f;
        for (int hv = 0; hv < pn; hv++)
            acc = fmaf(Ms[Y*pn + hv], tmp[(c*pn + hv)*32 + X], acc);
        if (addc) acc += g_hconst[b*32 + cg*4 + c];
        g_h32[((b*32 + cg*4 + c) << 10) + (Y << 5) + X] = acc;
    }
}

// ==== phi: 256 blocks x 256 thr, 4 co/block, 8-plane quarters; biasMul for merged scale ====
#define PHI_CI 1224   // 34*36
__global__ void __launch_bounds__(256, 4) k_phi(const float* __restrict__ wgt,
                                                const float* __restrict__ bias,
                                                int pn2, float biasMul) {
    extern __shared__ float sm[];
    float* in_s = sm;                      // 8*1224 = 9792 floats
    ull*   w2   = (ull*)(sm + 9792);       // 1152 ull
    int blk = blockIdx.x;
    int b = blk >> 3, cg = blk & 7, t = threadIdx.x;
    int pn22 = pn2*pn2;
    int s2 = 32 / pn2, s22 = s2*s2;
    float invp = 1.f / (float)s22;

    for (int i = blk*256 + t; i < 32*pn22; i += gridDim.x*256) g_best[i] = ~0ull;

    for (int i = t; i < 1152; i += 256) {
        float wv = wgt[cg*1152 + i]; w2[i] = pack2(wv, wv);
    }

    for (int i = t; i < 1600; i += 256) {
        int ci = i / 200, r = i - ci*200;
        int yy, xx;
        if (r < 36)      { yy = 0;       xx = r; }
        else if (r < 72) { yy = 33;      xx = r - 36; }
        else if (r < 104){ yy = r - 71;  xx = 0; }
        else { int q = r - 104; xx = 33 + (q >> 5); yy = 1 + (q & 31); }
        in_s[ci*PHI_CI + yy*36 + xx] = 0.f;
    }

    int y = t >> 3, x0 = (t & 7)*4;
    ull accA[4], accB[4];
    #pragma unroll
    for (int k = 0; k < 4; k++) {
        float bv = bias[cg*4 + k] * biasMul;
        ull bb = pack2(bv, bv); accA[k] = bb; accB[k] = bb;
    }
    const float* hb = g_h32 + (size_t)b*32768;

    for (int q4 = 0; q4 < 4; q4++) {
        __syncthreads();
        for (int i = t; i < 8192; i += 256) {
            int ci = i >> 10, p = i & 1023;
            in_s[ci*PHI_CI + ((p >> 5) + 1)*36 + (p & 31) + 1]
                = hb[((q4*8 + ci) << 10) + p];
        }
        __syncthreads();
        const ull* wbase = w2 + q4*72;
        const float* pbase = in_s + y*36 + x0;
        #pragma unroll
        for (int ci = 0; ci < 8; ci++) {
            #pragma unroll
            for (int rr = 0; rr < 3; rr++) {
                const float* row = pbase + rr*36;
                float4 u03 = *(const float4*)row;
                float2 u45 = *(const float2*)(row + 4);
                ull p0 = pack2(u03.x, u03.y);
                ull p1 = pack2(u03.y, u03.z);
                ull p2 = pack2(u03.z, u03.w);
                ull p3 = pack2(u03.w, u45.x);
                ull p4 = pack2(u45.x, u45.y);
                #pragma unroll
                for (int k = 0; k < 4; k++) {
                    ull w0 = wbase[k*288 + rr*3 + 0];
                    ull w1 = wbase[k*288 + rr*3 + 1];
                    ull wv2= wbase[k*288 + rr*3 + 2];
                    ull a = accA[k], c2 = accB[k];
                    a  = fma2(p0, w0, a);  a  = fma2(p1, w1, a);  a  = fma2(p2, wv2, a);
                    c2 = fma2(p2, w0, c2); c2 = fma2(p3, w1, c2); c2 = fma2(p4, wv2, c2);
                    accA[k] = a; accB[k] = c2;
                }
            }
            wbase += 9;
            pbase += PHI_CI;
        }
    }
    __syncthreads();

    #pragma unroll
    for (int k = 0; k < 4; k++) {
        float2 pa = unpack2(accA[k]);
        float2 pbv = unpack2(accB[k]);
        float conv[4] = {pa.x, pa.y, pbv.x, pbv.y};
        int co = cg*4 + k;
        #pragma unroll
        for (int q = 0; q < 4; q++) {
            int x = x0 + q;
            int gi = ((b*32 + co) << 10) + (y << 5) + x;
            float hval = g_h32[gi];
            float newv = g_frest[gi] - (0.5f*hval + 0.5f*conv[q]);
            g_frest[gi] = newv;
            in_s[k*1024 + (y << 5) + x] = newv;
        }
    }
    __syncthreads();
    if (pn2 < 32) {
        int w = t >> 5, l = t & 31;
        for (int o = w; o < 4*pn22; o += 8) {
            int kl = o / pn22, p = o - kl*pn22;
            int ph = p / pn2, pw2 = p - ph*pn2;
            float acc = 0.f;
            for (int e = l; e < s22; e += 32) {
                int dy = e / s2, dx = e - dy*s2;
                acc += in_s[kl*1024 + ((ph*s2 + dy) << 5) + (pw2*s2 + dx)];
            }
            #pragma unroll
            for (int off = 16; off; off >>= 1)
                acc += __shfl_down_sync(~0u, acc, off);
            if (l == 0)
                g_r[(b*32 + cg*4 + kl)*pn22 + p] = acc * invp;
        }
    }
}

// ================ hits for si=5 ================
__global__ void k_hits5() {
    for (int n = blockIdx.x*blockDim.x + threadIdx.x; n < 32768; n += gridDim.x*blockDim.x) {
        int idx = (int)(g_best[n] & 0xFFFull);
        atomicAdd(&g_hits[idx], 1.f);
    }
}

// ================ final ================
__global__ void k_final(float* __restrict__ out, int osz) {
    __shared__ float red[256];
    int t = threadIdx.x;
    red[t] = g_part[t] + g_part[t + 256]; __syncthreads();
    for (int o = 128; o > 0; o >>= 1) { if (t < o) red[t] += red[t+o]; __syncthreads(); }
    float S = red[0]; __syncthreads();
    float m = S / (float)NPIX;
    float h = 0.f;
    for (int k = 0; k < 16; k++) h += g_hits[t + k*256];
    red[t] = h; __syncthreads();
    for (int o = 128; o > 0; o >>= 1) { if (t < o) red[t] += red[t+o]; __syncthreads(); }
    float tot = red[0]; __syncthreads();
    float denom = fmaxf(tot, 1.f);
    float e = 0.f;
    for (int k = 0; k < 16; k++) {
        float p = g_hits[t + k*256] / denom;
        e += p * logf(p + 1e-10f);
    }
    red[t] = e; __syncthreads();
    for (int o = 128; o > 0; o >>= 1) { if (t < o) red[t] += red[t+o]; __syncthreads(); }
    if (t == 0) {
        float ent = red[0];
        float loss = 0.f;
        for (int si = 0; si < 6; si++) { loss = loss + 0.25f*m; loss = loss + m; }
        out[osz - 2] = loss;
        out[osz - 1] = expf(-ent);
    }
}

// ================ launcher ================
extern "C" void kernel_launch(void* const* d_in, const int* in_sizes, int n_in,
                              void* d_out, int out_size) {
    const float* f   = (const float*)d_in[0];
    const float* emb = (const float*)d_in[1];
    const float* pw  = (const float*)d_in[2];
    const float* pb  = (const float*)d_in[3];
    float* out = (float*)d_out;

    static int NBA = 0;
    if (NBA == 0) {
        int dev = 0; cudaGetDevice(&dev);
        int sms = 0;
        cudaDeviceGetAttribute(&sms, cudaDevAttrMultiProcessorCount, dev);
        if (sms <= 0) sms = 148;
        NBA = 2 * sms;
        cudaFuncSetAttribute(k_argmin, cudaFuncAttributeMaxDynamicSharedMemorySize, 82*1024);
        cudaFuncSetAttribute(k_phi,    cudaFuncAttributeMaxDynamicSharedMemorySize, 52*1024);
        cudaFuncSetAttribute(k_ups,    cudaFuncAttributeMaxDynamicSharedMemorySize, 16*1024);
    }

    const int pns[6]    = {1,2,4,8,16,32};
    const int phiSel[6] = {0,0,1,2,3,3};
    const int VSs[6]    = {128,128,32,64,16,4};

    k_prep<<<512, 256>>>((const float4*)f, (float4*)out, emb);

    for (int si = 0; si < 6; si++) {
        int pn = pns[si], pnpn = pn*pn, N = 32*pnpn;
        int VS = VSs[si], chunk = 4096 / VS;
        int TC = chunk < 512 ? chunk : 512;
        int mode, G, items;
        if (pn == 1) { mode = 0; G = 1; items = VS; }
        else {
            G = N / 64;
            items = G * VS;
            mode = (pn == 32) ? 2 : 1;
        }
        size_t smem = (size_t)TC*33*sizeof(float) + 8192 + 4096;
        int grid = items < NBA ? items : NBA;
        k_argmin<<<grid, 256, smem>>>(emb, pnpn, G, chunk, TC, items, mode);
        if (si == 0) {
            k_r1<<<32, 128>>>(emb, pw, pb);
        } else if (si < 5) {
            size_t us = (size_t)(4*pnpn + 4*pn*32 + 32*pn) * sizeof(float);
            k_ups<<<256, 256, us>>>(emb, pn, si, si == 1 ? 1 : 0);
            size_t ps = (size_t)(9792 + 2304) * sizeof(float);
            k_phi<<<256, 256, ps>>>(pw + phiSel[si]*9216, pb + phiSel[si]*32,
                                    pns[si+1], si == 1 ? 2.f : 1.f);
        }
    }
    k_hits5<<<128, 256>>>();
    k_final<<<1, 256>>>(out, out_size);
}

// round 17
// speedup vs baseline: 1.4833x; 1.0546x over previous
#include <cuda_runtime.h>
#include <math.h>
#include <float.h>

typedef unsigned long long ull;

#define NPIX (32*32*1024)
#define Vv 4096

// ---- static device scratch ----
__device__ float g_frest[NPIX];
__device__ float g_r[32*32*256];      // downsampled z, layout [(b*32+c)*pnpn + p]
__device__ float g_r2[4096];          // quadrant (2x2) means of f
__device__ float g_hconst[1024];      // h0 constant per (b,c)
__device__ float g_h32[NPIX];
__device__ float g_hits[Vv];
__device__ float g_esq[Vv];
__device__ float g_Mm[5][32][16];
__device__ float g_part[512];
__device__ ull   g_best[32768];

// ---- packed f32x2 helpers (FFMA2) ----
__device__ __forceinline__ ull pack2(float lo, float hi) {
    ull d;
    asm("mov.b64 %0, {%1, %2};" : "=l"(d)
        : "r"(__float_as_uint(lo)), "r"(__float_as_uint(hi)));
    return d;
}
__device__ __forceinline__ float2 unpack2(ull v) {
    unsigned int lo, hi;
    asm("mov.b64 {%0, %1}, %2;" : "=r"(lo), "=r"(hi) : "l"(v));
    return make_float2(__uint_as_float(lo), __uint_as_float(hi));
}
__device__ __forceinline__ ull fma2(ull a, ull b, ull c) {
    ull d;
    asm("fma.rn.f32x2 %0, %1, %2, %3;" : "=l"(d) : "l"(a), "l"(b), "l"(c));
    return d;
}
__device__ __forceinline__ ull add2(ull a, ull b) {
    ull d;
    asm("add.rn.f32x2 %0, %1, %2;" : "=l"(d) : "l"(a), "l"(b));
    return d;
}

__device__ __forceinline__ ull enc_key(float d, int idx) {
    unsigned u = __float_as_uint(d);
    u = (u & 0x80000000u) ? ~u : (u | 0x80000000u);
    return ((ull)u << 12) | (unsigned)idx;
}

// ================ prep ================
__global__ void __launch_bounds__(256) k_prep(const float4* __restrict__ f,
                                              float4* __restrict__ out4,
                                              const float* __restrict__ emb) {
    __shared__ float red[256];
    int t = threadIdx.x, blk = blockIdx.x;
    float s = 0.f;
    for (int i = blk*256 + t; i < NPIX/4; i += gridDim.x*256) {
        float4 v = f[i];
        ((float4*)g_frest)[i] = v;
        s = fmaf(v.x, v.x, fmaf(v.y, v.y, fmaf(v.z, v.z, fmaf(v.w, v.w, s))));
        out4[i] = make_float4(0.f, 0.f, 0.f, 0.f);
    }
    red[t] = s; __syncthreads();
    for (int o = 128; o > 0; o >>= 1) { if (t < o) red[t] += red[t+o]; __syncthreads(); }
    if (t == 0) g_part[blk] = red[0];

    {   // plane + quadrant means: one warp per (b,c) plane
        int gw = blk*8 + (t >> 5), l = t & 31;
        if (gw < 1024) {
            const float4* pf = f + gw*256;
            float s0 = 0.f, s1 = 0.f, s2 = 0.f, s3 = 0.f;
            for (int i = l; i < 256; i += 32) {
                float4 v = pf[i];
                float sv = (v.x + v.y) + (v.z + v.w);
                int q = (((i >> 3) >= 16) ? 2 : 0) + (((i & 7) >= 4) ? 1 : 0);
                if (q == 0) s0 += sv; else if (q == 1) s1 += sv;
                else if (q == 2) s2 += sv; else s3 += sv;
            }
            #pragma unroll
            for (int off = 16; off; off >>= 1) {
                s0 += __shfl_down_sync(~0u, s0, off);
                s1 += __shfl_down_sync(~0u, s1, off);
                s2 += __shfl_down_sync(~0u, s2, off);
                s3 += __shfl_down_sync(~0u, s3, off);
            }
            if (l == 0) {
                g_r[gw] = ((s0 + s1) + (s2 + s3)) * (1.f/1024.f);
                g_r2[gw*4 + 0] = s0 * (1.f/256.f);
                g_r2[gw*4 + 1] = s1 * (1.f/256.f);
                g_r2[gw*4 + 2] = s2 * (1.f/256.f);
                g_r2[gw*4 + 3] = s3 * (1.f/256.f);
            }
        }
    }
    for (int v = blk*256 + t; v < Vv; v += gridDim.x*256) {
        g_hits[v] = 0.f;
        const float* e = emb + v*32;
        float acc = 0.f;
        #pragma unroll
        for (int c = 0; c < 32; c++) acc += e[c]*e[c];
        g_esq[v] = acc;
    }
    if (blk == 0) {
        if (t < 160) {
            int si = t >> 5, r = t & 31;
            const int pns5[5] = {1,2,4,8,16};
            int pn = pns5[si];
            for (int j = 0; j < 16; j++) g_Mm[si][r][j] = 0.f;
            double scale = (double)pn / 32.0;
            double x = (r + 0.5)*scale - 0.5;
            double x0 = floor(x);
            double tt = x - x0;
            int ix0 = (int)x0;
            const double a = -0.75;
            for (int j = -1; j <= 2; j++) {
                double d = fabs(tt - (double)j);
                double w;
                if (d < 1.0)      w = (a+2.0)*d*d*d - (a+3.0)*d*d + 1.0;
                else if (d < 2.0) w = a*d*d*d - 5.0*a*d*d + 8.0*a*d - 4.0*a;
                else              w = 0.0;
                int col = ix0 + j;
                col = col < 0 ? 0 : (col > pn-1 ? pn-1 : col);
                g_Mm[si][r][col] = (float)((double)g_Mm[si][r][col] + w);
            }
        }
        if (t < 32) g_best[t] = ~0ull;
    }
}

// ================ k_r1: analytic r for scale 1 (merged phi0), hits0, g_best reset ================
__global__ void __launch_bounds__(128) k_r1(const float* __restrict__ emb,
                                            const float* __restrict__ wgt,
                                            const float* __restrict__ bias) {
    __shared__ float ws[9216];
    __shared__ float sv[32];
    __shared__ int sidx;
    int b = blockIdx.x, t = threadIdx.x;
    for (int i = t; i < 9216; i += 128) ws[i] = wgt[i];
    if (t == 0) {
        int idx = (int)(g_best[b] & 0xFFFull);
        sidx = idx;
        atomicAdd(&g_hits[idx], 1.f);
    }
    __syncthreads();
    if (t < 32) sv[t] = emb[sidx*32 + t];
    __syncthreads();
    int co = t >> 2, q = t & 3;
    float acc = 0.f;
    for (int ci = 0; ci < 32; ci++) {
        const float* w = ws + co*288 + ci*9;
        float w0=w[0],w1=w[1],w2=w[2],w3=w[3],w4=w[4],w5=w[5],w6=w[6],w7=w[7],w8=w[8];
        float Sf = ((w0+w1)+(w2+w3)) + ((w4+w5)+(w6+w7)) + w8;
        float top = w0+w1+w2, bot = w6+w7+w8, lef = w0+w3+w6, rig = w2+w5+w8;
        float D;
        if (q == 0)      D = 16.f*(top+lef) - w0;
        else if (q == 1) D = 16.f*(top+rig) - w2;
        else if (q == 2) D = 16.f*(bot+lef) - w6;
        else             D = 16.f*(bot+rig) - w8;
        acc = fmaf(sv[ci], Sf - D*(1.f/256.f), acc);
    }
    float vco = sv[co];
    float r = g_r2[(b*32 + co)*4 + q] - 0.5f*vco - 0.5f*acc - 0.5f*bias[co];
    g_r[(b*32 + co)*4 + q] = r;
    if (t < 32) g_hconst[b*32 + t] = sv[t];
    if (t < 4) g_best[b + t*32] = ~0ull;
}

// ================ argmin ================
__global__ void __launch_bounds__(256, 2) k_argmin(const float* __restrict__ emb,
                                                   int pnpn, int G, int chunk,
                                                   int TC, int items, int mode) {
    extern __shared__ float sm[];
    float4* es4   = (float4*)sm;
    float*  esq_s = sm + (size_t)TC*32;
    ull*    z2t   = (ull*)(sm + (size_t)TC*33);
    float*  sdA   = (float*)(z2t + 1024);
    float*  sdB   = sdA + 256;
    int*    svA   = (int*)(sdB + 256);
    int*    svB   = svA + 256;
    int t = threadIdx.x;

    if (mode == 0) {
        for (int item = blockIdx.x; item < items; item += gridDim.x) {
            __syncthreads();
            {
                int r = t >> 3, cq = (t & 7)*4;
                float zc[4];
                #pragma unroll
                for (int q = 0; q < 4; q++) zc[q] = g_r[r*32 + cq + q];
                int i0 = cq >> 1;
                z2t[i0*32 + r]     = pack2(zc[0], zc[1]);
                z2t[(i0+1)*32 + r] = pack2(zc[2], zc[3]);
            }
            __syncthreads();
            int w = t >> 5, l = t & 31;
            ull zp[16];
            #pragma unroll
            for (int i = 0; i < 16; i++) zp[i] = z2t[i*32 + l];
            float best = FLT_MAX; int bv = 0;
            int v0 = item*chunk;
            for (int t0 = v0; t0 < v0 + chunk; t0 += TC) {
                __syncthreads();
                const float4* eg = (const float4*)(emb + (size_t)t0*32);
                for (int i = t; i < TC*8; i += 256) es4[i] = eg[i];
                for (int i = t; i < TC;   i += 256) esq_s[i] = g_esq[t0 + i];
                __syncthreads();
                for (int v = w; v < TC; v += 8) {
                    const ulonglong2* evp = (const ulonglong2*)(es4 + v*8);
                    ull a0 = 0ull, a1 = 0ull;
                    #pragma unroll
                    for (int i = 0; i < 8; i++) {
                        ulonglong2 q = evp[i];
                        a0 = fma2(zp[2*i],   q.x, a0);
                        a1 = fma2(zp[2*i+1], q.y, a1);
                    }
                    float2 pq = unpack2(add2(a0, a1));
                    float dist = fmaf(-2.f, pq.x + pq.y, esq_s[v]);
                    if (dist < best) { best = dist; bv = t0 + v; }
                }
            }
            sdA[t] = best; svA[t] = bv;
            __syncthreads();
            if (w == 0) {
                float bb = sdA[l]; int vv = svA[l];
                #pragma unroll
                for (int k = 1; k < 8; k++) {
                    float d2 = sdA[k*32 + l]; int v2 = svA[k*32 + l];
                    if (d2 < bb || (d2 == bb && v2 < vv)) { bb = d2; vv = v2; }
                }
                atomicMin(&g_best[l], enc_key(bb, vv));
            }
        }
    } else {
        for (int item = blockIdx.x; item < items; item += gridDim.x) {
            __syncthreads();
            int g = item % G, vc = item / G;
            {
                int r = t >> 2, cq = (t & 3)*8;
                int n = g*64 + r;
                int b = n / pnpn, p = n - b*pnpn;
                float zc[8];
                if (mode == 2) {
                    #pragma unroll
                    for (int q = 0; q < 8; q++)
                        zc[q] = g_frest[((b*32 + cq + q) << 10) + p];
                } else {
                    #pragma unroll
                    for (int q = 0; q < 8; q++)
                        zc[q] = g_r[(b*32 + cq + q)*pnpn + p];
                }
                int i0 = cq >> 1;
                #pragma unroll
                for (int j = 0; j < 4; j++)
                    z2t[(i0+j)*64 + r] = pack2(zc[2*j], zc[2*j+1]);
            }
            __syncthreads();
            int w = t >> 5, l = t & 31;
            ull zpA[16], zpB[16];
            #pragma unroll
            for (int i = 0; i < 16; i++) {
                zpA[i] = z2t[i*64 + l];
                zpB[i] = z2t[i*64 + 32 + l];
            }
            float bestA = FLT_MAX, bestB = FLT_MAX; int bvA = 0, bvB = 0;
            int v0 = vc*chunk;
            for (int t0 = v0; t0 < v0 + chunk; t0 += TC) {
                __syncthreads();
                const float4* eg = (const float4*)(emb + (size_t)t0*32);
                for (int i = t; i < TC*8; i += 256) es4[i] = eg[i];
                for (int i = t; i < TC;   i += 256) esq_s[i] = g_esq[t0 + i];
                __syncthreads();
                for (int v = w; v < TC; v += 8) {
                    const ulonglong2* evp = (const ulonglong2*)(es4 + v*8);
                    ull a0 = 0ull, a1 = 0ull, b0 = 0ull, b1 = 0ull;
                    #pragma unroll
                    for (int i = 0; i < 8; i++) {
                        ulonglong2 q = evp[i];
                        a0 = fma2(zpA[2*i],   q.x, a0);
                        a1 = fma2(zpA[2*i+1], q.y, a1);
                        b0 = fma2(zpB[2*i],   q.x, b0);
                        b1 = fma2(zpB[2*i+1], q.y, b1);
                    }
                    float2 pa = unpack2(add2(a0, a1));
                    float dA = fmaf(-2.f, pa.x + pa.y, esq_s[v]);
                    float2 pbv = unpack2(add2(b0, b1));
                    float dB = fmaf(-2.f, pbv.x + pbv.y, esq_s[v]);
                    if (dA < bestA) { bestA = dA; bvA = t0 + v; }
                    if (dB < bestB) { bestB = dB; bvB = t0 + v; }
                }
            }
            sdA[t] = bestA; svA[t] = bvA; sdB[t] = bestB; svB[t] = bvB;
            __syncthreads();
            int w2i = t >> 5, l2 = t & 31;
            if (w2i == 0) {
                float bb = sdA[l2]; int vv = svA[l2];
                #pragma unroll
                for (int k = 1; k < 8; k++) {
                    float d2 = sdA[k*32 + l2]; int v2 = svA[k*32 + l2];
                    if (d2 < bb || (d2 == bb && v2 < vv)) { bb = d2; vv = v2; }
                }
                atomicMin(&g_best[g*64 + l2], enc_key(bb, vv));
            } else if (w2i == 1) {
                float bb = sdB[l2]; int vv = svB[l2];
                #pragma unroll
                for (int k = 1; k < 8; k++) {
                    float d2 = sdB[k*32 + l2]; int v2 = svB[k*32 + l2];
                    if (d2 < bb || (d2 == bb && v2 < vv)) { bb = d2; vv = v2; }
                }
                atomicMin(&g_best[g*64 + 32 + l2], enc_key(bb, vv));
            }
        }
    }
}

// ================ ups (addc: add constant h0 plane at si=1) ================
__global__ void __launch_bounds__(256) k_ups(const float* __restrict__ emb, int pn, int sidx,
                                             int addc) {
    extern __shared__ float sm[];
    int pnpn = pn * pn;
    float* hq  = sm;
    float* tmp = hq + 4*pnpn;
    float* Ms  = tmp + 4*pn*32;
    int b = blockIdx.x >> 3, cg = blockIdx.x & 7, t = threadIdx.x;
    for (int i = t; i < 32*pn; i += 256) Ms[i] = g_Mm[sidx][i/pn][i%pn];
    if (cg == 0) {
        for (int j = t; j < pnpn; j += 256) {
            int idx = (int)(g_best[b*pnpn + j] & 0xFFFull);
            atomicAdd(&g_hits[idx], 1.f);
        }
    }
    for (int j = t; j < 4*pnpn; j += 256) {
        int c = j / pnpn, p = j - c*pnpn;
        int idx = (int)(g_best[b*pnpn + p] & 0xFFFull);
        hq[j] = emb[(size_t)idx*32 + cg*4 + c];
    }
    __syncthreads();
    for (int j = t; j < 4*pn*32; j += 256) {
        int c = j / (pn*32); int rem = j - c*(pn*32);
        int h = rem >> 5; int X = rem & 31;
        float acc = 0.f;
        for (int wv = 0; wv < pn; wv++)
            acc = fmaf(Ms[X*pn + wv], hq[c*pnpn + h*pn + wv], acc);
        tmp[j] = acc;
    }
    __syncthreads();
    for (int j = t; j < 4096; j += 256) {
        int c = j >> 10, Y = (j >> 5) & 31, X = j & 31;
        float acc = 0.f;
        for (int hv = 0; hv < pn; hv++)
            acc = fmaf(Ms[Y*pn + hv], tmp[(c*pn + hv)*32 + X], acc);
        if (addc) acc += g_hconst[b*32 + cg*4 + c];
        g_h32[((b*32 + cg*4 + c) << 10) + (Y << 5) + X] = acc;
    }
}

// ==== phi: HALF-IMAGE blocks — grid 512 x 128 thr, 4 co x 16 rows/block ====
// in_s: 8 planes x 18 rows x 36 cols (stride 648); smem ~29.3KB -> many resident blocks
__global__ void __launch_bounds__(128, 6) k_phi(const float* __restrict__ wgt,
                                                const float* __restrict__ bias,
                                                int pn2, float biasMul) {
    extern __shared__ float sm[];
    float* in_s = sm;                      // 8*648 = 5184 floats
    ull*   w2   = (ull*)(sm + 5184);       // 1152 ull = 9216 B
    int blk = blockIdx.x;
    int half = blk & 1, cg = (blk >> 1) & 7, b = blk >> 4;
    int t = threadIdx.x;
    int pn22 = pn2*pn2;
    int s2 = 32 / pn2, s22 = s2*s2;
    float invp = 1.f / (float)s22;

    // reset g_best for next scale (grid 512 x 128 = 65536 >= 32768)
    for (int i = blk*128 + t; i < 32*pn22; i += gridDim.x*128) g_best[i] = ~0ull;

    // weights: 4 co x 288, packed (w,w)
    for (int i = t; i < 1152; i += 128) {
        float wv = wgt[cg*1152 + i]; w2[i] = pack2(wv, wv);
    }

    // zero halo: cols 0 & 33 (18 rows each) + the out-of-image boundary row, per plane
    for (int i = t; i < 576; i += 128) {
        int ci = i / 72, r = i - ci*72;
        int rl, xx;
        if (r < 18)      { rl = r;        xx = 0; }
        else if (r < 36) { rl = r - 18;   xx = 33; }
        else             { rl = half ? 17 : 0; xx = r - 36; }
        in_s[ci*648 + rl*36 + xx] = 0.f;
    }

    int yl = t >> 3;              // 0..15 local row
    int x0 = (t & 7) * 4;
    int yg = half*16 + yl;        // global row
    ull accA[4], accB[4];
    #pragma unroll
    for (int k = 0; k < 4; k++) {
        float bv = bias[cg*4 + k] * biasMul;
        ull bb = pack2(bv, bv); accA[k] = bb; accB[k] = bb;
    }
    const float* hb = g_h32 + (size_t)b*32768;
    int grbase = half*16 - 1;

    for (int q4 = 0; q4 < 4; q4++) {
        __syncthreads();
        // load 18 input rows (grbase..grbase+17), zero-predicated at image edges
        for (int i = t; i < 4608; i += 128) {
            int ci = i / 576; int rem = i - ci*576;
            int rr = rem >> 5, x = rem & 31;
            int gr = grbase + rr;
            float v = 0.f;
            if (gr >= 0 && gr < 32)
                v = hb[((q4*8 + ci) << 10) + (gr << 5) + x];
            in_s[ci*648 + rr*36 + x + 1] = v;
        }
        __syncthreads();
        const ull* wbase = w2 + q4*72;
        const float* pbase = in_s + yl*36 + x0;   // input row y-1 => local row yl
        #pragma unroll
        for (int ci = 0; ci < 8; ci++) {
            #pragma unroll
            for (int rr = 0; rr < 3; rr++) {
                const float* row = pbase + rr*36;   // 16B aligned
                float4 u03 = *(const float4*)row;
                float2 u45 = *(const float2*)(row + 4);
                ull p0 = pack2(u03.x, u03.y);
                ull p1 = pack2(u03.y, u03.z);
                ull p2 = pack2(u03.z, u03.w);
                ull p3 = pack2(u03.w, u45.x);
                ull p4 = pack2(u45.x, u45.y);
                #pragma unroll
                for (int k = 0; k < 4; k++) {
                    ull w0 = wbase[k*288 + rr*3 + 0];
                    ull w1 = wbase[k*288 + rr*3 + 1];
                    ull wv2= wbase[k*288 + rr*3 + 2];
                    ull a = accA[k], c2 = accB[k];
                    a  = fma2(p0, w0, a);  a  = fma2(p1, w1, a);  a  = fma2(p2, wv2, a);
                    c2 = fma2(p2, w0, c2); c2 = fma2(p3, w1, c2); c2 = fma2(p4, wv2, c2);
                    accA[k] = a; accB[k] = c2;
                }
            }
            wbase += 9;
            pbase += 648;
        }
    }
    __syncthreads();   // done reading in_s; reuse as pooling stage (4co x 16rows x 32)

    #pragma unroll
    for (int k = 0; k < 4; k++) {
        float2 pa = unpack2(accA[k]);
        float2 pbv = unpack2(accB[k]);
        float conv[4] = {pa.x, pa.y, pbv.x, pbv.y};
        int co = cg*4 + k;
        #pragma unroll
        for (int q = 0; q < 4; q++) {
            int x = x0 + q;
            int gi = ((b*32 + co) << 10) + (yg << 5) + x;
            float hval = g_h32[gi];
            float newv = g_frest[gi] - (0.5f*hval + 0.5f*conv[q]);
            g_frest[gi] = newv;
            in_s[k*512 + (yl << 5) + x] = newv;
        }
    }
    __syncthreads();
    if (pn2 < 32) {
        // pool within this half: s2 <= 8, pooled rows [half*pn2/2, ...)
        int pn22h = pn22 >> 1;
        int phbase = half * (pn2 >> 1);
        for (int idx = t; idx < 4*pn22h; idx += 128) {
            int kl = idx / pn22h; int pc = idx - kl*pn22h;
            int phl = pc / pn2, pw2 = pc - phl*pn2;
            float acc = 0.f;
            for (int dy = 0; dy < s2; dy++)
                for (int dx = 0; dx < s2; dx++)
                    acc += in_s[kl*512 + ((phl*s2 + dy) << 5) + pw2*s2 + dx];
            g_r[(b*32 + cg*4 + kl)*pn22 + (phbase + phl)*pn2 + pw2] = acc * invp;
        }
    }
}

// ================ hits for si=5 ================
__global__ void k_hits5() {
    for (int n = blockIdx.x*blockDim.x + threadIdx.x; n < 32768; n += gridDim.x*blockDim.x) {
        int idx = (int)(g_best[n] & 0xFFFull);
        atomicAdd(&g_hits[idx], 1.f);
    }
}

// ================ final ================
__global__ void k_final(float* __restrict__ out, int osz) {
    __shared__ float red[256];
    int t = threadIdx.x;
    red[t] = g_part[t] + g_part[t + 256]; __syncthreads();
    for (int o = 128; o > 0; o >>= 1) { if (t < o) red[t] += red[t+o]; __syncthreads(); }
    float S = red[0]; __syncthreads();
    float m = S / (float)NPIX;
    float h = 0.f;
    for (int k = 0; k < 16; k++) h += g_hits[t + k*256];
    red[t] = h; __syncthreads();
    for (int o = 128; o > 0; o >>= 1) { if (t < o) red[t] += red[t+o]; __syncthreads(); }
    float tot = red[0]; __syncthreads();
    float denom = fmaxf(tot, 1.f);
    float e = 0.f;
    for (int k = 0; k < 16; k++) {
        float p = g_hits[t + k*256] / denom;
        e += p * logf(p + 1e-10f);
    }
    red[t] = e; __syncthreads();
    for (int o = 128; o > 0; o >>= 1) { if (t < o) red[t] += red[t+o]; __syncthreads(); }
    if (t == 0) {
        float ent = red[0];
        float loss = 0.f;
        for (int si = 0; si < 6; si++) { loss = loss + 0.25f*m; loss = loss + m; }
        out[osz - 2] = loss;
        out[osz - 1] = expf(-ent);
    }
}

// ================ launcher ================
extern "C" void kernel_launch(void* const* d_in, const int* in_sizes, int n_in,
                              void* d_out, int out_size) {
    const float* f   = (const float*)d_in[0];
    const float* emb = (const float*)d_in[1];
    const float* pw  = (const float*)d_in[2];
    const float* pb  = (const float*)d_in[3];
    float* out = (float*)d_out;

    static int NBA = 0;
    if (NBA == 0) {
        int dev = 0; cudaGetDevice(&dev);
        int sms = 0;
        cudaDeviceGetAttribute(&sms, cudaDevAttrMultiProcessorCount, dev);
        if (sms <= 0) sms = 148;
        NBA = 2 * sms;
        cudaFuncSetAttribute(k_argmin, cudaFuncAttributeMaxDynamicSharedMemorySize, 82*1024);
        cudaFuncSetAttribute(k_phi,    cudaFuncAttributeMaxDynamicSharedMemorySize, 32*1024);
        cudaFuncSetAttribute(k_ups,    cudaFuncAttributeMaxDynamicSharedMemorySize, 16*1024);
    }

    const int pns[6]    = {1,2,4,8,16,32};
    const int phiSel[6] = {0,0,1,2,3,3};
    const int VSs[6]    = {128,128,32,64,16,4};

    k_prep<<<512, 256>>>((const float4*)f, (float4*)out, emb);

    for (int si = 0; si < 6; si++) {
        int pn = pns[si], pnpn = pn*pn, N = 32*pnpn;
        int VS = VSs[si], chunk = 4096 / VS;
        int TC = chunk < 512 ? chunk : 512;
        int mode, G, items;
        if (pn == 1) { mode = 0; G = 1; items = VS; }
        else {
            G = N / 64;
            items = G * VS;
            mode = (pn == 32) ? 2 : 1;
        }
        size_t smem = (size_t)TC*33*sizeof(float) + 8192 + 4096;
        int grid = items < NBA ? items : NBA;
        k_argmin<<<grid, 256, smem>>>(emb, pnpn, G, chunk, TC, items, mode);
        if (si == 0) {
            k_r1<<<32, 128>>>(emb, pw, pb);
        } else if (si < 5) {
            size_t us = (size_t)(4*pnpn + 4*pn*32 + 32*pn) * sizeof(float);
            k_ups<<<256, 256, us>>>(emb, pn, si, si == 1 ? 1 : 0);
            size_t ps = (size_t)(5184*4 + 9216);
            k_phi<<<512, 128, ps>>>(pw + phiSel[si]*9216, pb + phiSel[si]*32,
                                    pns[si+1], si == 1 ? 2.f : 1.f);
        }
    }
    k_hits5<<<128, 256>>>();
    k_final<<<1, 256>>>(out, out_size);
}